// round 1
// baseline (speedup 1.0000x reference)
#include <cuda_runtime.h>
#include <cstdint>

// Problem constants
#define B_  8
#define L_  2048
#define E_  1024
#define H_  16
#define D_  64
#define M_  (B_ * L_)        // 16384 rows
#define NBH (B_ * H_)        // 128 head-batches
#define PI_HALF 1.5707963267948966f

// ---------------- device scratch (no allocations allowed) ----------------
__device__ float g_q[(size_t)M_ * E_];
__device__ float g_k[(size_t)M_ * E_];
__device__ float g_v[(size_t)M_ * E_];
__device__ float g_attn[(size_t)M_ * E_];          // rows indexed l*B + b
__device__ float g_kv[(size_t)NBH * 128 * 64];     // per head: (2D=128, D=64)
__device__ float g_ksum[NBH * 128];
__device__ float g_sv[NBH * 64];                   // sum_l sin_l * v
__device__ float g_cv[NBH * 64];                   // sum_l cos_l * v
__device__ float g_sc[NBH * 2];                    // (sum sin, sum cos)

// ---------------- SGEMM: C[M,1024] = A[M,1024] @ W[1024,1024] + bias ------
// 128x128 block tile, BK=8, 256 threads, 8x8 per-thread microtile.
__device__ __forceinline__ void sgemm_body(const float* __restrict__ A,
                                           const float* __restrict__ W,
                                           const float* __restrict__ bias,
                                           float* __restrict__ C) {
    const int K = E_, N = E_;
    __shared__ float As[8][128];
    __shared__ float Bs[8][128];

    const int tid  = threadIdx.x;
    const int trow = tid >> 4;          // 0..15
    const int tcol = tid & 15;          // 0..15
    const int arow = tid >> 1;          // 0..127
    const int acol = (tid & 1) << 2;    // 0 or 4
    const int wrow = tid >> 5;          // 0..7
    const int wcol = (tid & 31) << 2;   // 0..124

    const float* Ag = A + (size_t)blockIdx.y * 128 * K;
    const float* Wg = W + blockIdx.x * 128;

    float acc[8][8];
#pragma unroll
    for (int i = 0; i < 8; i++)
#pragma unroll
        for (int j = 0; j < 8; j++) acc[i][j] = 0.f;

    for (int k0 = 0; k0 < K; k0 += 8) {
        float4 av = *(const float4*)(Ag + (size_t)arow * K + k0 + acol);
        As[acol + 0][arow] = av.x;
        As[acol + 1][arow] = av.y;
        As[acol + 2][arow] = av.z;
        As[acol + 3][arow] = av.w;
        *(float4*)(&Bs[wrow][wcol]) =
            *(const float4*)(Wg + (size_t)(k0 + wrow) * N + wcol);
        __syncthreads();
#pragma unroll
        for (int kk = 0; kk < 8; kk++) {
            float ra[8], rb[8];
#pragma unroll
            for (int i = 0; i < 8; i++) ra[i] = As[kk][trow * 8 + i];
#pragma unroll
            for (int j = 0; j < 8; j++) rb[j] = Bs[kk][tcol * 8 + j];
#pragma unroll
            for (int i = 0; i < 8; i++)
#pragma unroll
                for (int j = 0; j < 8; j++) acc[i][j] += ra[i] * rb[j];
        }
        __syncthreads();
    }

    const int ccol = blockIdx.x * 128 + tcol * 8;
    float4 b0 = *(const float4*)(bias + ccol);
    float4 b1 = *(const float4*)(bias + ccol + 4);
#pragma unroll
    for (int i = 0; i < 8; i++) {
        size_t row = (size_t)(blockIdx.y * 128 + trow * 8 + i);
        float4 o0 = make_float4(acc[i][0] + b0.x, acc[i][1] + b0.y,
                                acc[i][2] + b0.z, acc[i][3] + b0.w);
        float4 o1 = make_float4(acc[i][4] + b1.x, acc[i][5] + b1.y,
                                acc[i][6] + b1.z, acc[i][7] + b1.w);
        *(float4*)(C + row * N + ccol)     = o0;
        *(float4*)(C + row * N + ccol + 4) = o1;
    }
}

__global__ __launch_bounds__(256) void qkv_gemm(const float* __restrict__ X,
                                                const float* __restrict__ Wq,
                                                const float* __restrict__ bq,
                                                const float* __restrict__ Wk,
                                                const float* __restrict__ bk,
                                                const float* __restrict__ Wv,
                                                const float* __restrict__ bv) {
    const float* W; const float* bias; float* C;
    if (blockIdx.z == 0)      { W = Wq; bias = bq; C = g_q; }
    else if (blockIdx.z == 1) { W = Wk; bias = bk; C = g_k; }
    else                      { W = Wv; bias = bv; C = g_v; }
    sgemm_body(X, W, bias, C);
}

__global__ __launch_bounds__(256) void oproj_gemm(const float* __restrict__ Wo,
                                                  const float* __restrict__ bo,
                                                  float* __restrict__ out) {
    sgemm_body(g_attn, Wo, bo, out);
}

// ---------------- Kernel 2: per-head KV reduction over L ------------------
// Per (b,h): kv[i][j] = sum_l kf[l][i] * v[l][j]  (i in 0..127, j in 0..63)
// plus ksum[i], sv[j]=sum sin*v, cv[j]=sum cos*v, ssum, csum.
__global__ __launch_bounds__(256) void kv_reduce() {
    const int bh = blockIdx.x;
    const int b = bh / H_, h = bh % H_;

    __shared__ float kf_s[8][128];
    __shared__ float v_s[8][64];
    __shared__ float sins[8], coss[8];

    const int t = threadIdx.x;
    const int w = t >> 5, lane = t & 31;
    const int ti = t >> 4;   // 0..15 -> i0 = ti*8
    const int tj = t & 15;   // 0..15 -> j0 = tj*4

    float acc[8][4];
#pragma unroll
    for (int i = 0; i < 8; i++)
#pragma unroll
        for (int j = 0; j < 4; j++) acc[i][j] = 0.f;
    float ksum_r = 0.f, sv_r = 0.f, cv_r = 0.f, ssum_r = 0.f, csum_r = 0.f;

    const float* Kp = g_k + (size_t)b * L_ * E_ + h * D_;
    const float* Vp = g_v + (size_t)b * L_ * E_ + h * D_;
    const float angk = PI_HALF / (float)L_;

    for (int l = 0; l < L_; l += 8) {
        const int pos = l + w;
        float sn, cs;
        __sincosf(angk * (float)(pos + 1), &sn, &cs);
        const size_t roff = (size_t)pos * E_;
        float k0 = Kp[roff + lane];
        float k1 = Kp[roff + lane + 32];
        float m = fmaxf(k0, k1);
#pragma unroll
        for (int o = 16; o; o >>= 1) m = fmaxf(m, __shfl_xor_sync(0xffffffffu, m, o));
        float e0 = __expf(k0 - m), e1 = __expf(k1 - m);
        float s = e0 + e1;
#pragma unroll
        for (int o = 16; o; o >>= 1) s += __shfl_xor_sync(0xffffffffu, s, o);
        float inv = 1.f / s;
        float s0 = e0 * inv, s1 = e1 * inv;
        kf_s[w][lane]      = s0 * sn;
        kf_s[w][lane + 32] = s1 * sn;
        kf_s[w][lane + 64] = s0 * cs;
        kf_s[w][lane + 96] = s1 * cs;
        v_s[w][lane]      = Vp[roff + lane];
        v_s[w][lane + 32] = Vp[roff + lane + 32];
        if (lane == 0) { sins[w] = sn; coss[w] = cs; }
        __syncthreads();

#pragma unroll
        for (int p = 0; p < 8; p++) {
            float4 vv = *(const float4*)&v_s[p][tj * 4];
#pragma unroll
            for (int ii = 0; ii < 8; ii++) {
                float kf = kf_s[p][ti * 8 + ii];
                acc[ii][0] += kf * vv.x;
                acc[ii][1] += kf * vv.y;
                acc[ii][2] += kf * vv.z;
                acc[ii][3] += kf * vv.w;
            }
        }
        if (t < 128) {
#pragma unroll
            for (int p = 0; p < 8; p++) ksum_r += kf_s[p][t];
        } else if (t < 192) {
#pragma unroll
            for (int p = 0; p < 8; p++) sv_r += sins[p] * v_s[p][t - 128];
        } else {
#pragma unroll
            for (int p = 0; p < 8; p++) cv_r += coss[p] * v_s[p][t - 192];
        }
        if (t == 0) {
#pragma unroll
            for (int p = 0; p < 8; p++) ssum_r += sins[p];
        }
        if (t == 1) {
#pragma unroll
            for (int p = 0; p < 8; p++) csum_r += coss[p];
        }
        __syncthreads();
    }

    float* KVp = g_kv + (size_t)bh * 128 * 64;
#pragma unroll
    for (int ii = 0; ii < 8; ii++)
        *(float4*)(KVp + (ti * 8 + ii) * 64 + tj * 4) =
            make_float4(acc[ii][0], acc[ii][1], acc[ii][2], acc[ii][3]);
    if (t < 128) g_ksum[bh * 128 + t] = ksum_r;
    else if (t < 192) g_sv[bh * 64 + t - 128] = sv_r;
    else g_cv[bh * 64 + t - 192] = cv_r;
    if (t == 0) g_sc[bh * 2 + 0] = ssum_r;
    if (t == 1) g_sc[bh * 2 + 1] = csum_r;
}

// ---------------- Kernel 3: apply qf @ kv with normalization --------------
// Writes A rows indexed (l*B + b), cols h*D + d.
__global__ __launch_bounds__(256) void attn_apply() {
    const int bh = blockIdx.x;
    const int b = bh / H_, h = bh % H_;
    const int lbase = blockIdx.y * 128;

    __shared__ float kv_s[128][64];
    __shared__ float ksum_s[128], cksum_s[128];
    __shared__ float sv_s[64], cv_s[64];
    __shared__ float qf_s[8][128], cqf_s[8][128];
    __shared__ float zs[8][2];
    __shared__ float sins[8], coss[8];

    const int t = threadIdx.x;
    const int w = t >> 5, lane = t & 31;

    const float* KVp = g_kv + (size_t)bh * 8192;
    for (int i = t; i < 2048; i += 256)
        *(float4*)(&kv_s[0][0] + i * 4) = *(const float4*)(KVp + i * 4);
    if (t < 128) {
        float ks = g_ksum[bh * 128 + t];
        ksum_s[t] = ks;
        float base = (t < 64) ? g_sc[bh * 2] : g_sc[bh * 2 + 1];
        cksum_s[t] = base - ks;
    } else if (t < 192) {
        sv_s[t - 128] = g_sv[bh * 64 + t - 128];
    } else {
        cv_s[t - 192] = g_cv[bh * 64 + t - 192];
    }
    __syncthreads();

    const float* Qp = g_q + (size_t)b * L_ * E_ + h * D_;
    const float angk = PI_HALF / (float)L_;

    for (int lc = 0; lc < 128; lc += 8) {
        const int pos = lbase + lc + w;
        float sn, cs;
        __sincosf(angk * (float)(pos + 1), &sn, &cs);
        const size_t roff = (size_t)pos * E_;
        float q0 = Qp[roff + lane];
        float q1 = Qp[roff + lane + 32];
        float m = fmaxf(q0, q1);
#pragma unroll
        for (int o = 16; o; o >>= 1) m = fmaxf(m, __shfl_xor_sync(0xffffffffu, m, o));
        float e0 = __expf(q0 - m), e1 = __expf(q1 - m);
        float s = e0 + e1;
#pragma unroll
        for (int o = 16; o; o >>= 1) s += __shfl_xor_sync(0xffffffffu, s, o);
        float inv = 1.f / s;
        float s0 = e0 * inv, s1 = e1 * inv;
        float f0 = s0 * sn, f1 = s1 * sn, f2 = s0 * cs, f3 = s1 * cs;
        float c0 = (1.f - s0) * sn, c1 = (1.f - s1) * sn;
        float c2 = (1.f - s0) * cs, c3 = (1.f - s1) * cs;
        qf_s[w][lane]       = f0;  qf_s[w][lane + 32]  = f1;
        qf_s[w][lane + 64]  = f2;  qf_s[w][lane + 96]  = f3;
        cqf_s[w][lane]      = c0;  cqf_s[w][lane + 32] = c1;
        cqf_s[w][lane + 64] = c2;  cqf_s[w][lane + 96] = c3;
        float d1 = f0 * ksum_s[lane] + f1 * ksum_s[lane + 32] +
                   f2 * ksum_s[lane + 64] + f3 * ksum_s[lane + 96];
        float d2 = c0 * cksum_s[lane] + c1 * cksum_s[lane + 32] +
                   c2 * cksum_s[lane + 64] + c3 * cksum_s[lane + 96];
#pragma unroll
        for (int o = 16; o; o >>= 1) {
            d1 += __shfl_xor_sync(0xffffffffu, d1, o);
            d2 += __shfl_xor_sync(0xffffffffu, d2, o);
        }
        if (lane == 0) {
            zs[w][0] = 1.f / fmaxf(d1, 1e-6f);
            zs[w][1] = 1.f / fmaxf(d2, 1e-6f);
            sins[w] = sn; coss[w] = cs;
        }
        __syncthreads();

        // phase 2: thread -> (p = w, d pair = lane*2)
        const int p = w;
        const int d0 = lane * 2;
        float a1x = 0.f, a1y = 0.f, a2x = 0.f, a2y = 0.f;
#pragma unroll
        for (int i = 0; i < 128; i += 4) {
            float4 f4 = *(const float4*)&qf_s[p][i];
            float4 c4 = *(const float4*)&cqf_s[p][i];
            float2 k0v = *(const float2*)&kv_s[i + 0][d0];
            float2 k1v = *(const float2*)&kv_s[i + 1][d0];
            float2 k2v = *(const float2*)&kv_s[i + 2][d0];
            float2 k3v = *(const float2*)&kv_s[i + 3][d0];
            a1x += f4.x * k0v.x; a1y += f4.x * k0v.y;
            a2x += c4.x * k0v.x; a2y += c4.x * k0v.y;
            a1x += f4.y * k1v.x; a1y += f4.y * k1v.y;
            a2x += c4.y * k1v.x; a2y += c4.y * k1v.y;
            a1x += f4.z * k2v.x; a1y += f4.z * k2v.y;
            a2x += c4.z * k2v.x; a2y += c4.z * k2v.y;
            a1x += f4.w * k3v.x; a1y += f4.w * k3v.y;
            a2x += c4.w * k3v.x; a2y += c4.w * k3v.y;
        }
        float z1 = zs[p][0], z2 = zs[p][1];
        float S1 = 63.f * sins[p], S2 = 63.f * coss[p];
        float o0 = z1 * a1x + z2 * (sv_s[d0] * S1 + cv_s[d0] * S2 - a2x);
        float o1 = z1 * a1y + z2 * (sv_s[d0 + 1] * S1 + cv_s[d0 + 1] * S2 - a2y);
        const int posl = lbase + lc + p;
        float* Op = g_attn + ((size_t)posl * B_ + b) * E_ + h * D_ + d0;
        *(float2*)Op = make_float2(o0, o1);
        __syncthreads();
    }
}

// ---------------- launch ---------------------------------------------------
extern "C" void kernel_launch(void* const* d_in, const int* in_sizes, int n_in,
                              void* d_out, int out_size) {
    const float* X  = (const float*)d_in[0];
    const float* Wq = (const float*)d_in[1];
    const float* bq = (const float*)d_in[2];
    const float* Wk = (const float*)d_in[3];
    const float* bk = (const float*)d_in[4];
    const float* Wv = (const float*)d_in[5];
    const float* bv = (const float*)d_in[6];
    const float* Wo = (const float*)d_in[7];
    const float* bo = (const float*)d_in[8];
    float* out = (float*)d_out;

    dim3 gq(E_ / 128, M_ / 128, 3);     // (8, 128, 3)
    qkv_gemm<<<gq, 256>>>(X, Wq, bq, Wk, bk, Wv, bv);
    kv_reduce<<<NBH, 256>>>();
    attn_apply<<<dim3(NBH, L_ / 128), 256>>>();
    dim3 go(E_ / 128, M_ / 128);        // (8, 128)
    oproj_gemm<<<go, 256>>>(Wo, bo, out);
}

// round 3
// speedup vs baseline: 1.6418x; 1.6418x over previous
#include <cuda_runtime.h>
#include <cuda_bf16.h>
#include <cstdint>

// Problem constants
#define B_  8
#define L_  2048
#define E_  1024
#define H_  16
#define D_  64
#define M_  (B_ * L_)        // 16384 rows
#define NBH (B_ * H_)        // 128 head-batches
#define PI_HALF 1.5707963267948966f

// ---------------- device scratch (no allocations allowed) ----------------
__device__ float g_q[(size_t)M_ * E_];
__device__ float g_k[(size_t)M_ * E_];
__device__ float g_v[(size_t)M_ * E_];
__device__ __nv_bfloat16 g_xhi[(size_t)M_ * E_];
__device__ __nv_bfloat16 g_xlo[(size_t)M_ * E_];
__device__ __nv_bfloat16 g_ahi[(size_t)M_ * E_];   // attn out hi (rows l*B+b)
__device__ __nv_bfloat16 g_alo[(size_t)M_ * E_];   // attn out lo
__device__ __nv_bfloat16 g_wthi[4ull * E_ * E_];   // W^T hi, per matrix [n][k]
__device__ __nv_bfloat16 g_wtlo[4ull * E_ * E_];
__device__ float g_kv[(size_t)NBH * 128 * 64];
__device__ float g_ksum[NBH * 128];
__device__ float g_sv[NBH * 64];
__device__ float g_cv[NBH * 64];
__device__ float g_sc[NBH * 2];

// ---------------- PTX helpers ----------------------------------------------
#define CP16(dst, src) \
    asm volatile("cp.async.cg.shared.global [%0], [%1], 16;" :: "r"(dst), "l"(src))

#define LDSM4(r, addr) \
    asm volatile("ldmatrix.sync.aligned.m8n8.x4.shared.b16 {%0,%1,%2,%3}, [%4];" \
                 : "=r"((r)[0]), "=r"((r)[1]), "=r"((r)[2]), "=r"((r)[3]) : "r"(addr))

#define MMA_BF16(d, a, b0, b1) \
    asm volatile("mma.sync.aligned.m16n8k16.row.col.f32.bf16.bf16.f32 " \
                 "{%0,%1,%2,%3},{%4,%5,%6,%7},{%8,%9},{%0,%1,%2,%3};" \
                 : "+f"((d)[0]), "+f"((d)[1]), "+f"((d)[2]), "+f"((d)[3]) \
                 : "r"((a)[0]), "r"((a)[1]), "r"((a)[2]), "r"((a)[3]), \
                   "r"(b0), "r"(b1))

// ---------------- conversions ----------------------------------------------
__device__ __forceinline__ void split_bf16(float v, __nv_bfloat16& h, __nv_bfloat16& l) {
    h = __float2bfloat16(v);
    l = __float2bfloat16(v - __bfloat162float(h));
}

__global__ __launch_bounds__(256) void convert_x(const float* __restrict__ X) {
    size_t i = ((size_t)blockIdx.x * 256 + threadIdx.x) * 4;
    float4 v = *(const float4*)(X + i);
    __nv_bfloat16 h0, h1, h2, h3, l0, l1, l2, l3;
    split_bf16(v.x, h0, l0); split_bf16(v.y, h1, l1);
    split_bf16(v.z, h2, l2); split_bf16(v.w, h3, l3);
    *(__nv_bfloat162*)(g_xhi + i)     = __nv_bfloat162(h0, h1);
    *(__nv_bfloat162*)(g_xhi + i + 2) = __nv_bfloat162(h2, h3);
    *(__nv_bfloat162*)(g_xlo + i)     = __nv_bfloat162(l0, l1);
    *(__nv_bfloat162*)(g_xlo + i + 2) = __nv_bfloat162(l2, l3);
}

// transpose + split: W[k][n] (fp32, n contiguous) -> WT[n][k] bf16 hi/lo
__global__ void convert_w(const float* __restrict__ Wq, const float* __restrict__ Wk,
                          const float* __restrict__ Wv, const float* __restrict__ Wo) {
    const float* W = (blockIdx.z == 0) ? Wq : (blockIdx.z == 1) ? Wk
                   : (blockIdx.z == 2) ? Wv : Wo;
    __shared__ float t[32][33];
    const int nb = blockIdx.x * 32, kb = blockIdx.y * 32;
    const int tx = threadIdx.x, ty = threadIdx.y;
#pragma unroll
    for (int i = 0; i < 4; i++)
        t[ty + 8 * i][tx] = W[(size_t)(kb + ty + 8 * i) * E_ + nb + tx];
    __syncthreads();
    __nv_bfloat16* Oh = g_wthi + (size_t)blockIdx.z * E_ * E_;
    __nv_bfloat16* Ol = g_wtlo + (size_t)blockIdx.z * E_ * E_;
#pragma unroll
    for (int i = 0; i < 4; i++) {
        int n = nb + ty + 8 * i, k = kb + tx;
        float v = t[tx][ty + 8 * i];
        __nv_bfloat16 h, l;
        split_bf16(v, h, l);
        Oh[(size_t)n * E_ + k] = h;
        Ol[(size_t)n * E_ + k] = l;
    }
}

// ---------------- HMMA GEMM: C[128m,128n] = A(hi,lo) @ B(hi,lo)^T + bias ---
// A,B: bf16 K-major [rows][1024]. BK=32, 3-stage cp.async, mma.sync bf16.
#define BK 32
#define STAGES 3
#define TROW 80                        // smem bytes per row (32 bf16 + pad)
#define TILE_BYTES (128 * TROW)        // 10240
#define STAGE_BYTES (4 * TILE_BYTES)   // Ahi, Alo, Bhi, Blo = 40960
#define DSMEM (STAGES * STAGE_BYTES)   // 122880
#define NCHUNK 32                      // 1024 / BK

__device__ __forceinline__ void gemm_tile(
    const __nv_bfloat16* __restrict__ Ahi, const __nv_bfloat16* __restrict__ Alo,
    const __nv_bfloat16* __restrict__ Bhi, const __nv_bfloat16* __restrict__ Blo,
    const float* __restrict__ bias, float* __restrict__ C,
    int mBase, int nBase)
{
    extern __shared__ char smem[];
    const uint32_t sbase = (uint32_t)__cvta_generic_to_shared(smem);
    const int tid = threadIdx.x;
    const int lane = tid & 31, wid = tid >> 5;
    const int wm = wid & 3, wn = wid >> 2;   // warp tile: 32m x 64n

    // load mapping: 8 x 16B chunks per thread per stage (4 tiles of 128x32 bf16)
    const __nv_bfloat16* gp[8];
    uint32_t soff[8];
#pragma unroll
    for (int i = 0; i < 8; i++) {
        const int cid  = i * 256 + tid;
        const int tile = cid >> 9;         // 0..3
        const int ci   = cid & 511;
        const int row  = ci >> 2;
        const int ch   = ci & 3;
        const __nv_bfloat16* base = (tile == 0) ? Ahi : (tile == 1) ? Alo
                                   : (tile == 2) ? Bhi : Blo;
        const int grow = ((tile < 2) ? mBase : nBase) + row;
        gp[i]   = base + (size_t)grow * E_ + ch * 8;
        soff[i] = (uint32_t)(tile * TILE_BYTES + row * TROW + ch * 16);
    }

    float acc[2][8][4];
#pragma unroll
    for (int mt = 0; mt < 2; mt++)
#pragma unroll
        for (int nt = 0; nt < 8; nt++)
#pragma unroll
            for (int j = 0; j < 4; j++) acc[mt][nt][j] = 0.f;

    // prologue: chunks 0,1
#pragma unroll
    for (int c = 0; c < 2; c++) {
        const uint32_t sb = sbase + c * STAGE_BYTES;
#pragma unroll
        for (int i = 0; i < 8; i++) CP16(sb + soff[i], gp[i] + c * BK);
        asm volatile("cp.async.commit_group;" ::: "memory");
    }

    for (int c = 0; c < NCHUNK; c++) {
        asm volatile("cp.async.wait_group 1;" ::: "memory");
        __syncthreads();

        if (c + 2 < NCHUNK) {
            const uint32_t sb = sbase + (uint32_t)(((c + 2) % STAGES) * STAGE_BYTES);
            const size_t koff = (size_t)(c + 2) * BK;
#pragma unroll
            for (int i = 0; i < 8; i++) CP16(sb + soff[i], gp[i] + koff);
        }
        asm volatile("cp.async.commit_group;" ::: "memory");

        const uint32_t st = sbase + (uint32_t)((c % STAGES) * STAGE_BYTES);
#pragma unroll
        for (int ks = 0; ks < 2; ks++) {
            uint32_t ah[2][4], al[2][4], bh[4][4], bl[4][4];
#pragma unroll
            for (int mt = 0; mt < 2; mt++) {
                const uint32_t ad = st + (uint32_t)((wm * 32 + mt * 16 + (lane & 15)) * TROW
                                  + (ks * 2 + (lane >> 4)) * 16);
                LDSM4(ah[mt], ad);
                LDSM4(al[mt], ad + TILE_BYTES);
            }
#pragma unroll
            for (int nt = 0; nt < 4; nt++) {
                const uint32_t bd = st + 2 * TILE_BYTES
                                  + (uint32_t)((wn * 64 + nt * 16 + (lane & 15)) * TROW
                                  + (ks * 2 + (lane >> 4)) * 16);
                LDSM4(bh[nt], bd);
                LDSM4(bl[nt], bd + TILE_BYTES);
            }
#pragma unroll
            for (int mt = 0; mt < 2; mt++)
#pragma unroll
                for (int nt = 0; nt < 4; nt++) {
                    MMA_BF16(acc[mt][nt * 2],     ah[mt], bh[nt][0], bh[nt][2]);
                    MMA_BF16(acc[mt][nt * 2],     ah[mt], bl[nt][0], bl[nt][2]);
                    MMA_BF16(acc[mt][nt * 2],     al[mt], bh[nt][0], bh[nt][2]);
                    MMA_BF16(acc[mt][nt * 2 + 1], ah[mt], bh[nt][1], bh[nt][3]);
                    MMA_BF16(acc[mt][nt * 2 + 1], ah[mt], bl[nt][1], bl[nt][3]);
                    MMA_BF16(acc[mt][nt * 2 + 1], al[mt], bh[nt][1], bh[nt][3]);
                }
        }
    }

    // epilogue
    const int r0 = lane >> 2, cq = (lane & 3) * 2;
#pragma unroll
    for (int mt = 0; mt < 2; mt++)
#pragma unroll
        for (int nt8 = 0; nt8 < 8; nt8++) {
            const int col = nBase + wn * 64 + nt8 * 8 + cq;
            const float2 bv = *(const float2*)(bias + col);
            const int row = mBase + wm * 32 + mt * 16 + r0;
            float* cp0 = C + (size_t)row * E_ + col;
            *(float2*)cp0 = make_float2(acc[mt][nt8][0] + bv.x, acc[mt][nt8][1] + bv.y);
            float* cp1 = cp0 + 8 * E_;
            *(float2*)cp1 = make_float2(acc[mt][nt8][2] + bv.x, acc[mt][nt8][3] + bv.y);
        }
}

__global__ __launch_bounds__(256, 1) void qkv_mma(const float* __restrict__ bq,
                                                  const float* __restrict__ bk,
                                                  const float* __restrict__ bv) {
    const int z = blockIdx.z;
    const float* bias = (z == 0) ? bq : (z == 1) ? bk : bv;
    float* C = (z == 0) ? g_q : (z == 1) ? g_k : g_v;
    gemm_tile(g_xhi, g_xlo,
              g_wthi + (size_t)z * E_ * E_, g_wtlo + (size_t)z * E_ * E_,
              bias, C, blockIdx.y * 128, blockIdx.x * 128);
}

__global__ __launch_bounds__(256, 1) void oproj_mma(const float* __restrict__ bo,
                                                    float* __restrict__ out) {
    gemm_tile(g_ahi, g_alo,
              g_wthi + 3ull * E_ * E_, g_wtlo + 3ull * E_ * E_,
              bo, out, blockIdx.y * 128, blockIdx.x * 128);
}

// ---------------- Kernel: per-head KV reduction over L ---------------------
__global__ __launch_bounds__(256) void kv_reduce() {
    const int bh = blockIdx.x;
    const int b = bh / H_, h = bh % H_;

    __shared__ float kf_s[8][128];
    __shared__ float v_s[8][64];
    __shared__ float sins[8], coss[8];

    const int t = threadIdx.x;
    const int w = t >> 5, lane = t & 31;
    const int ti = t >> 4;
    const int tj = t & 15;

    float acc[8][4];
#pragma unroll
    for (int i = 0; i < 8; i++)
#pragma unroll
        for (int j = 0; j < 4; j++) acc[i][j] = 0.f;
    float ksum_r = 0.f, sv_r = 0.f, cv_r = 0.f, ssum_r = 0.f, csum_r = 0.f;

    const float* Kp = g_k + (size_t)b * L_ * E_ + h * D_;
    const float* Vp = g_v + (size_t)b * L_ * E_ + h * D_;
    const float angk = PI_HALF / (float)L_;

    for (int l = 0; l < L_; l += 8) {
        const int pos = l + w;
        float sn, cs;
        __sincosf(angk * (float)(pos + 1), &sn, &cs);
        const size_t roff = (size_t)pos * E_;
        float k0 = Kp[roff + lane];
        float k1 = Kp[roff + lane + 32];
        float m = fmaxf(k0, k1);
#pragma unroll
        for (int o = 16; o; o >>= 1) m = fmaxf(m, __shfl_xor_sync(0xffffffffu, m, o));
        float e0 = __expf(k0 - m), e1 = __expf(k1 - m);
        float s = e0 + e1;
#pragma unroll
        for (int o = 16; o; o >>= 1) s += __shfl_xor_sync(0xffffffffu, s, o);
        float inv = 1.f / s;
        float s0 = e0 * inv, s1 = e1 * inv;
        kf_s[w][lane]      = s0 * sn;
        kf_s[w][lane + 32] = s1 * sn;
        kf_s[w][lane + 64] = s0 * cs;
        kf_s[w][lane + 96] = s1 * cs;
        v_s[w][lane]      = Vp[roff + lane];
        v_s[w][lane + 32] = Vp[roff + lane + 32];
        if (lane == 0) { sins[w] = sn; coss[w] = cs; }
        __syncthreads();

#pragma unroll
        for (int p = 0; p < 8; p++) {
            float4 vv = *(const float4*)&v_s[p][tj * 4];
#pragma unroll
            for (int ii = 0; ii < 8; ii++) {
                float kf = kf_s[p][ti * 8 + ii];
                acc[ii][0] += kf * vv.x;
                acc[ii][1] += kf * vv.y;
                acc[ii][2] += kf * vv.z;
                acc[ii][3] += kf * vv.w;
            }
        }
        if (t < 128) {
#pragma unroll
            for (int p = 0; p < 8; p++) ksum_r += kf_s[p][t];
        } else if (t < 192) {
#pragma unroll
            for (int p = 0; p < 8; p++) sv_r += sins[p] * v_s[p][t - 128];
        } else {
#pragma unroll
            for (int p = 0; p < 8; p++) cv_r += coss[p] * v_s[p][t - 192];
        }
        if (t == 0) {
#pragma unroll
            for (int p = 0; p < 8; p++) ssum_r += sins[p];
        }
        if (t == 1) {
#pragma unroll
            for (int p = 0; p < 8; p++) csum_r += coss[p];
        }
        __syncthreads();
    }

    float* KVp = g_kv + (size_t)bh * 128 * 64;
#pragma unroll
    for (int ii = 0; ii < 8; ii++)
        *(float4*)(KVp + (ti * 8 + ii) * 64 + tj * 4) =
            make_float4(acc[ii][0], acc[ii][1], acc[ii][2], acc[ii][3]);
    if (t < 128) g_ksum[bh * 128 + t] = ksum_r;
    else if (t < 192) g_sv[bh * 64 + t - 128] = sv_r;
    else g_cv[bh * 64 + t - 192] = cv_r;
    if (t == 0) g_sc[bh * 2 + 0] = ssum_r;
    if (t == 1) g_sc[bh * 2 + 1] = csum_r;
}

// ---------------- Kernel: apply qf @ kv with normalization -----------------
__global__ __launch_bounds__(256) void attn_apply() {
    const int bh = blockIdx.x;
    const int b = bh / H_, h = bh % H_;
    const int lbase = blockIdx.y * 128;

    __shared__ float kv_s[128][64];
    __shared__ float ksum_s[128], cksum_s[128];
    __shared__ float sv_s[64], cv_s[64];
    __shared__ float qf_s[8][128], cqf_s[8][128];
    __shared__ float zs[8][2];
    __shared__ float sins[8], coss[8];

    const int t = threadIdx.x;
    const int w = t >> 5, lane = t & 31;

    const float* KVp = g_kv + (size_t)bh * 8192;
    for (int i = t; i < 2048; i += 256)
        *(float4*)(&kv_s[0][0] + i * 4) = *(const float4*)(KVp + i * 4);
    if (t < 128) {
        float ks = g_ksum[bh * 128 + t];
        ksum_s[t] = ks;
        float base = (t < 64) ? g_sc[bh * 2] : g_sc[bh * 2 + 1];
        cksum_s[t] = base - ks;
    } else if (t < 192) {
        sv_s[t - 128] = g_sv[bh * 64 + t - 128];
    } else {
        cv_s[t - 192] = g_cv[bh * 64 + t - 192];
    }
    __syncthreads();

    const float* Qp = g_q + (size_t)b * L_ * E_ + h * D_;
    const float angk = PI_HALF / (float)L_;

    for (int lc = 0; lc < 128; lc += 8) {
        const int pos = lbase + lc + w;
        float sn, cs;
        __sincosf(angk * (float)(pos + 1), &sn, &cs);
        const size_t roff = (size_t)pos * E_;
        float q0 = Qp[roff + lane];
        float q1 = Qp[roff + lane + 32];
        float m = fmaxf(q0, q1);
#pragma unroll
        for (int o = 16; o; o >>= 1) m = fmaxf(m, __shfl_xor_sync(0xffffffffu, m, o));
        float e0 = __expf(q0 - m), e1 = __expf(q1 - m);
        float s = e0 + e1;
#pragma unroll
        for (int o = 16; o; o >>= 1) s += __shfl_xor_sync(0xffffffffu, s, o);
        float inv = 1.f / s;
        float s0 = e0 * inv, s1 = e1 * inv;
        float f0 = s0 * sn, f1 = s1 * sn, f2 = s0 * cs, f3 = s1 * cs;
        float c0 = (1.f - s0) * sn, c1 = (1.f - s1) * sn;
        float c2 = (1.f - s0) * cs, c3 = (1.f - s1) * cs;
        qf_s[w][lane]       = f0;  qf_s[w][lane + 32]  = f1;
        qf_s[w][lane + 64]  = f2;  qf_s[w][lane + 96]  = f3;
        cqf_s[w][lane]      = c0;  cqf_s[w][lane + 32] = c1;
        cqf_s[w][lane + 64] = c2;  cqf_s[w][lane + 96] = c3;
        float d1 = f0 * ksum_s[lane] + f1 * ksum_s[lane + 32] +
                   f2 * ksum_s[lane + 64] + f3 * ksum_s[lane + 96];
        float d2 = c0 * cksum_s[lane] + c1 * cksum_s[lane + 32] +
                   c2 * cksum_s[lane + 64] + c3 * cksum_s[lane + 96];
#pragma unroll
        for (int o = 16; o; o >>= 1) {
            d1 += __shfl_xor_sync(0xffffffffu, d1, o);
            d2 += __shfl_xor_sync(0xffffffffu, d2, o);
        }
        if (lane == 0) {
            zs[w][0] = 1.f / fmaxf(d1, 1e-6f);
            zs[w][1] = 1.f / fmaxf(d2, 1e-6f);
            sins[w] = sn; coss[w] = cs;
        }
        __syncthreads();

        const int p = w;
        const int d0 = lane * 2;
        float a1x = 0.f, a1y = 0.f, a2x = 0.f, a2y = 0.f;
#pragma unroll
        for (int i = 0; i < 128; i += 4) {
            float4 f4 = *(const float4*)&qf_s[p][i];
            float4 c4 = *(const float4*)&cqf_s[p][i];
            float2 k0v = *(const float2*)&kv_s[i + 0][d0];
            float2 k1v = *(const float2*)&kv_s[i + 1][d0];
            float2 k2v = *(const float2*)&kv_s[i + 2][d0];
            float2 k3v = *(const float2*)&kv_s[i + 3][d0];
            a1x += f4.x * k0v.x; a1y += f4.x * k0v.y;
            a2x += c4.x * k0v.x; a2y += c4.x * k0v.y;
            a1x += f4.y * k1v.x; a1y += f4.y * k1v.y;
            a2x += c4.y * k1v.x; a2y += c4.y * k1v.y;
            a1x += f4.z * k2v.x; a1y += f4.z * k2v.y;
            a2x += c4.z * k2v.x; a2y += c4.z * k2v.y;
            a1x += f4.w * k3v.x; a1y += f4.w * k3v.y;
            a2x += c4.w * k3v.x; a2y += c4.w * k3v.y;
        }
        float z1 = zs[p][0], z2 = zs[p][1];
        float S1 = 63.f * sins[p], S2 = 63.f * coss[p];
        float o0 = z1 * a1x + z2 * (sv_s[d0] * S1 + cv_s[d0] * S2 - a2x);
        float o1 = z1 * a1y + z2 * (sv_s[d0 + 1] * S1 + cv_s[d0 + 1] * S2 - a2y);
        const int posl = lbase + lc + p;
        const size_t oidx = ((size_t)posl * B_ + b) * E_ + h * D_ + d0;
        __nv_bfloat16 h0, h1, l0v, l1v;
        split_bf16(o0, h0, l0v);
        split_bf16(o1, h1, l1v);
        *(__nv_bfloat162*)(g_ahi + oidx) = __nv_bfloat162(h0, h1);
        *(__nv_bfloat162*)(g_alo + oidx) = __nv_bfloat162(l0v, l1v);
        __syncthreads();
    }
}

// ---------------- launch ----------------------------------------------------
extern "C" void kernel_launch(void* const* d_in, const int* in_sizes, int n_in,
                              void* d_out, int out_size) {
    const float* X  = (const float*)d_in[0];
    const float* Wq = (const float*)d_in[1];
    const float* bq = (const float*)d_in[2];
    const float* Wk = (const float*)d_in[3];
    const float* bk = (const float*)d_in[4];
    const float* Wv = (const float*)d_in[5];
    const float* bv = (const float*)d_in[6];
    const float* Wo = (const float*)d_in[7];
    const float* bo = (const float*)d_in[8];
    float* out = (float*)d_out;

    cudaFuncSetAttribute(qkv_mma, cudaFuncAttributeMaxDynamicSharedMemorySize, DSMEM);
    cudaFuncSetAttribute(oproj_mma, cudaFuncAttributeMaxDynamicSharedMemorySize, DSMEM);

    convert_x<<<(M_ * E_) / (256 * 4), 256>>>(X);
    convert_w<<<dim3(32, 32, 4), dim3(32, 8)>>>(Wq, Wk, Wv, Wo);
    qkv_mma<<<dim3(8, 128, 3), 256, DSMEM>>>(bq, bk, bv);
    kv_reduce<<<NBH, 256>>>();
    attn_apply<<<dim3(NBH, L_ / 128), 256>>>();
    oproj_mma<<<dim3(8, 128), 256, DSMEM>>>(bo, out);
}

// round 4
// speedup vs baseline: 1.9618x; 1.1949x over previous
#include <cuda_runtime.h>
#include <cuda_bf16.h>
#include <cstdint>

// Problem constants
#define B_  8
#define L_  2048
#define E_  1024
#define H_  16
#define D_  64
#define M_  (B_ * L_)        // 16384 rows
#define NBH (B_ * H_)        // 128 head-batches
#define NSPLIT 8
#define LSPL (L_ / NSPLIT)   // 256
#define PI_HALF 1.5707963267948966f

// ---------------- device scratch (no allocations allowed) ----------------
__device__ float g_q[(size_t)M_ * E_];
__device__ float g_k[(size_t)M_ * E_];
__device__ float g_v[(size_t)M_ * E_];
__device__ __nv_bfloat16 g_xhi[(size_t)M_ * E_];
__device__ __nv_bfloat16 g_xlo[(size_t)M_ * E_];
__device__ __nv_bfloat16 g_ahi[(size_t)M_ * E_];   // attn out hi (rows l*B+b)
__device__ __nv_bfloat16 g_alo[(size_t)M_ * E_];   // attn out lo
__device__ __nv_bfloat16 g_wthi[4ull * E_ * E_];   // W^T hi, per matrix [n][k]
__device__ __nv_bfloat16 g_wtlo[4ull * E_ * E_];
__device__ float g_kv[(size_t)NBH * 128 * 64];
__device__ float g_ksum[NBH * 128];
__device__ float g_P1[NBH * 64];                   // 63*sv - KS1
__device__ float g_P2[NBH * 64];                   // 63*cv - KS2
__device__ float g_Q[NBH * 2];                     // 63*ssum-S1k, 63*csum-S2k
// split partials
__device__ float g_kvp[(size_t)NSPLIT * NBH * 128 * 64];
__device__ float g_ksump[NSPLIT * NBH * 128];
__device__ float g_svp[NSPLIT * NBH * 64];
__device__ float g_cvp[NSPLIT * NBH * 64];
__device__ float g_scp[NSPLIT * NBH * 2];

// ---------------- PTX helpers ----------------------------------------------
#define CP16(dst, src) \
    asm volatile("cp.async.cg.shared.global [%0], [%1], 16;" :: "r"(dst), "l"(src))

#define LDSM4(r, addr) \
    asm volatile("ldmatrix.sync.aligned.m8n8.x4.shared.b16 {%0,%1,%2,%3}, [%4];" \
                 : "=r"((r)[0]), "=r"((r)[1]), "=r"((r)[2]), "=r"((r)[3]) : "r"(addr))

#define MMA_BF16(d, a, b0, b1) \
    asm volatile("mma.sync.aligned.m16n8k16.row.col.f32.bf16.bf16.f32 " \
                 "{%0,%1,%2,%3},{%4,%5,%6,%7},{%8,%9},{%0,%1,%2,%3};" \
                 : "+f"((d)[0]), "+f"((d)[1]), "+f"((d)[2]), "+f"((d)[3]) \
                 : "r"((a)[0]), "r"((a)[1]), "r"((a)[2]), "r"((a)[3]), \
                   "r"(b0), "r"(b1))

// ---------------- conversions ----------------------------------------------
__device__ __forceinline__ void split_bf16(float v, __nv_bfloat16& h, __nv_bfloat16& l) {
    h = __float2bfloat16(v);
    l = __float2bfloat16(v - __bfloat162float(h));
}

__global__ __launch_bounds__(256) void convert_x(const float* __restrict__ X) {
    size_t i = ((size_t)blockIdx.x * 256 + threadIdx.x) * 4;
    float4 v = *(const float4*)(X + i);
    __nv_bfloat16 h0, h1, h2, h3, l0, l1, l2, l3;
    split_bf16(v.x, h0, l0); split_bf16(v.y, h1, l1);
    split_bf16(v.z, h2, l2); split_bf16(v.w, h3, l3);
    *(__nv_bfloat162*)(g_xhi + i)     = __nv_bfloat162(h0, h1);
    *(__nv_bfloat162*)(g_xhi + i + 2) = __nv_bfloat162(h2, h3);
    *(__nv_bfloat162*)(g_xlo + i)     = __nv_bfloat162(l0, l1);
    *(__nv_bfloat162*)(g_xlo + i + 2) = __nv_bfloat162(l2, l3);
}

// transpose + split: W[k][n] (fp32, n contiguous) -> WT[n][k] bf16 hi/lo
__global__ void convert_w(const float* __restrict__ Wq, const float* __restrict__ Wk,
                          const float* __restrict__ Wv, const float* __restrict__ Wo) {
    const float* W = (blockIdx.z == 0) ? Wq : (blockIdx.z == 1) ? Wk
                   : (blockIdx.z == 2) ? Wv : Wo;
    __shared__ float t[32][33];
    const int nb = blockIdx.x * 32, kb = blockIdx.y * 32;
    const int tx = threadIdx.x, ty = threadIdx.y;
#pragma unroll
    for (int i = 0; i < 4; i++)
        t[ty + 8 * i][tx] = W[(size_t)(kb + ty + 8 * i) * E_ + nb + tx];
    __syncthreads();
    __nv_bfloat16* Oh = g_wthi + (size_t)blockIdx.z * E_ * E_;
    __nv_bfloat16* Ol = g_wtlo + (size_t)blockIdx.z * E_ * E_;
#pragma unroll
    for (int i = 0; i < 4; i++) {
        int n = nb + ty + 8 * i, k = kb + tx;
        float v = t[tx][ty + 8 * i];
        __nv_bfloat16 h, l;
        split_bf16(v, h, l);
        Oh[(size_t)n * E_ + k] = h;
        Ol[(size_t)n * E_ + k] = l;
    }
}

// ---------------- HMMA GEMM: C[128m,128n] = A(hi,lo) @ B(hi,lo)^T + bias ---
#define BK 32
#define STAGES 3
#define TROW 80
#define TILE_BYTES (128 * TROW)
#define STAGE_BYTES (4 * TILE_BYTES)
#define DSMEM (STAGES * STAGE_BYTES)
#define NCHUNK 32

__device__ __forceinline__ void gemm_tile(
    const __nv_bfloat16* __restrict__ Ahi, const __nv_bfloat16* __restrict__ Alo,
    const __nv_bfloat16* __restrict__ Bhi, const __nv_bfloat16* __restrict__ Blo,
    const float* __restrict__ bias, float* __restrict__ C,
    int mBase, int nBase)
{
    extern __shared__ char smem[];
    const uint32_t sbase = (uint32_t)__cvta_generic_to_shared(smem);
    const int tid = threadIdx.x;
    const int lane = tid & 31, wid = tid >> 5;
    const int wm = wid & 3, wn = wid >> 2;

    const __nv_bfloat16* gp[8];
    uint32_t soff[8];
#pragma unroll
    for (int i = 0; i < 8; i++) {
        const int cid  = i * 256 + tid;
        const int tile = cid >> 9;
        const int ci   = cid & 511;
        const int row  = ci >> 2;
        const int ch   = ci & 3;
        const __nv_bfloat16* base = (tile == 0) ? Ahi : (tile == 1) ? Alo
                                   : (tile == 2) ? Bhi : Blo;
        const int grow = ((tile < 2) ? mBase : nBase) + row;
        gp[i]   = base + (size_t)grow * E_ + ch * 8;
        soff[i] = (uint32_t)(tile * TILE_BYTES + row * TROW + ch * 16);
    }

    float acc[2][8][4];
#pragma unroll
    for (int mt = 0; mt < 2; mt++)
#pragma unroll
        for (int nt = 0; nt < 8; nt++)
#pragma unroll
            for (int j = 0; j < 4; j++) acc[mt][nt][j] = 0.f;

#pragma unroll
    for (int c = 0; c < 2; c++) {
        const uint32_t sb = sbase + c * STAGE_BYTES;
#pragma unroll
        for (int i = 0; i < 8; i++) CP16(sb + soff[i], gp[i] + c * BK);
        asm volatile("cp.async.commit_group;" ::: "memory");
    }

    for (int c = 0; c < NCHUNK; c++) {
        asm volatile("cp.async.wait_group 1;" ::: "memory");
        __syncthreads();

        if (c + 2 < NCHUNK) {
            const uint32_t sb = sbase + (uint32_t)(((c + 2) % STAGES) * STAGE_BYTES);
            const size_t koff = (size_t)(c + 2) * BK;
#pragma unroll
            for (int i = 0; i < 8; i++) CP16(sb + soff[i], gp[i] + koff);
        }
        asm volatile("cp.async.commit_group;" ::: "memory");

        const uint32_t st = sbase + (uint32_t)((c % STAGES) * STAGE_BYTES);
#pragma unroll
        for (int ks = 0; ks < 2; ks++) {
            uint32_t ah[2][4], al[2][4], bh[4][4], bl[4][4];
#pragma unroll
            for (int mt = 0; mt < 2; mt++) {
                const uint32_t ad = st + (uint32_t)((wm * 32 + mt * 16 + (lane & 15)) * TROW
                                  + (ks * 2 + (lane >> 4)) * 16);
                LDSM4(ah[mt], ad);
                LDSM4(al[mt], ad + TILE_BYTES);
            }
#pragma unroll
            for (int nt = 0; nt < 4; nt++) {
                const uint32_t bd = st + 2 * TILE_BYTES
                                  + (uint32_t)((wn * 64 + nt * 16 + (lane & 15)) * TROW
                                  + (ks * 2 + (lane >> 4)) * 16);
                LDSM4(bh[nt], bd);
                LDSM4(bl[nt], bd + TILE_BYTES);
            }
#pragma unroll
            for (int mt = 0; mt < 2; mt++)
#pragma unroll
                for (int nt = 0; nt < 4; nt++) {
                    MMA_BF16(acc[mt][nt * 2],     ah[mt], bh[nt][0], bh[nt][2]);
                    MMA_BF16(acc[mt][nt * 2],     ah[mt], bl[nt][0], bl[nt][2]);
                    MMA_BF16(acc[mt][nt * 2],     al[mt], bh[nt][0], bh[nt][2]);
                    MMA_BF16(acc[mt][nt * 2 + 1], ah[mt], bh[nt][1], bh[nt][3]);
                    MMA_BF16(acc[mt][nt * 2 + 1], ah[mt], bl[nt][1], bl[nt][3]);
                    MMA_BF16(acc[mt][nt * 2 + 1], al[mt], bh[nt][1], bh[nt][3]);
                }
        }
    }

    const int r0 = lane >> 2, cq = (lane & 3) * 2;
#pragma unroll
    for (int mt = 0; mt < 2; mt++)
#pragma unroll
        for (int nt8 = 0; nt8 < 8; nt8++) {
            const int col = nBase + wn * 64 + nt8 * 8 + cq;
            const float2 bv = *(const float2*)(bias + col);
            const int row = mBase + wm * 32 + mt * 16 + r0;
            float* cp0 = C + (size_t)row * E_ + col;
            *(float2*)cp0 = make_float2(acc[mt][nt8][0] + bv.x, acc[mt][nt8][1] + bv.y);
            float* cp1 = cp0 + 8 * E_;
            *(float2*)cp1 = make_float2(acc[mt][nt8][2] + bv.x, acc[mt][nt8][3] + bv.y);
        }
}

__global__ __launch_bounds__(256, 1) void qkv_mma(const float* __restrict__ bq,
                                                  const float* __restrict__ bk,
                                                  const float* __restrict__ bv) {
    const int z = blockIdx.z;
    const float* bias = (z == 0) ? bq : (z == 1) ? bk : bv;
    float* C = (z == 0) ? g_q : (z == 1) ? g_k : g_v;
    gemm_tile(g_xhi, g_xlo,
              g_wthi + (size_t)z * E_ * E_, g_wtlo + (size_t)z * E_ * E_,
              bias, C, blockIdx.y * 128, blockIdx.x * 128);
}

__global__ __launch_bounds__(256, 1) void oproj_mma(const float* __restrict__ bo,
                                                    float* __restrict__ out) {
    gemm_tile(g_ahi, g_alo,
              g_wthi + 3ull * E_ * E_, g_wtlo + 3ull * E_ * E_,
              bo, out, blockIdx.y * 128, blockIdx.x * 128);
}

// ---------------- KV reduction (split over L) ------------------------------
__global__ __launch_bounds__(256) void kv_reduce_part() {
    const int bh = blockIdx.x;
    const int sp = blockIdx.y;
    const int b = bh / H_, h = bh % H_;
    const int pbase = sp * NBH + bh;

    __shared__ float kf_s[8][128];
    __shared__ float v_s[8][64];
    __shared__ float sins[8], coss[8];

    const int t = threadIdx.x;
    const int w = t >> 5, lane = t & 31;
    const int ti = t >> 4;
    const int tj = t & 15;

    float acc[8][4];
#pragma unroll
    for (int i = 0; i < 8; i++)
#pragma unroll
        for (int j = 0; j < 4; j++) acc[i][j] = 0.f;
    float ksum_r = 0.f, sv_r = 0.f, cv_r = 0.f, ssum_r = 0.f, csum_r = 0.f;

    const float* Kp = g_k + (size_t)b * L_ * E_ + h * D_;
    const float* Vp = g_v + (size_t)b * L_ * E_ + h * D_;
    const float angk = PI_HALF / (float)L_;

    for (int l = sp * LSPL; l < (sp + 1) * LSPL; l += 8) {
        const int pos = l + w;
        float sn, cs;
        __sincosf(angk * (float)(pos + 1), &sn, &cs);
        const size_t roff = (size_t)pos * E_;
        float k0 = Kp[roff + lane];
        float k1 = Kp[roff + lane + 32];
        float m = fmaxf(k0, k1);
#pragma unroll
        for (int o = 16; o; o >>= 1) m = fmaxf(m, __shfl_xor_sync(0xffffffffu, m, o));
        float e0 = __expf(k0 - m), e1 = __expf(k1 - m);
        float s = e0 + e1;
#pragma unroll
        for (int o = 16; o; o >>= 1) s += __shfl_xor_sync(0xffffffffu, s, o);
        float inv = 1.f / s;
        float s0 = e0 * inv, s1 = e1 * inv;
        kf_s[w][lane]      = s0 * sn;
        kf_s[w][lane + 32] = s1 * sn;
        kf_s[w][lane + 64] = s0 * cs;
        kf_s[w][lane + 96] = s1 * cs;
        v_s[w][lane]      = Vp[roff + lane];
        v_s[w][lane + 32] = Vp[roff + lane + 32];
        if (lane == 0) { sins[w] = sn; coss[w] = cs; }
        __syncthreads();

#pragma unroll
        for (int p = 0; p < 8; p++) {
            float4 vv = *(const float4*)&v_s[p][tj * 4];
#pragma unroll
            for (int ii = 0; ii < 8; ii++) {
                float kf = kf_s[p][ti * 8 + ii];
                acc[ii][0] += kf * vv.x;
                acc[ii][1] += kf * vv.y;
                acc[ii][2] += kf * vv.z;
                acc[ii][3] += kf * vv.w;
            }
        }
        if (t < 128) {
#pragma unroll
            for (int p = 0; p < 8; p++) ksum_r += kf_s[p][t];
        } else if (t < 192) {
#pragma unroll
            for (int p = 0; p < 8; p++) sv_r += sins[p] * v_s[p][t - 128];
        } else {
#pragma unroll
            for (int p = 0; p < 8; p++) cv_r += coss[p] * v_s[p][t - 192];
        }
        if (t == 0) {
#pragma unroll
            for (int p = 0; p < 8; p++) ssum_r += sins[p];
        }
        if (t == 1) {
#pragma unroll
            for (int p = 0; p < 8; p++) csum_r += coss[p];
        }
        __syncthreads();
    }

    float* KVp = g_kvp + (size_t)pbase * 8192;
#pragma unroll
    for (int ii = 0; ii < 8; ii++)
        *(float4*)(KVp + (ti * 8 + ii) * 64 + tj * 4) =
            make_float4(acc[ii][0], acc[ii][1], acc[ii][2], acc[ii][3]);
    if (t < 128) g_ksump[pbase * 128 + t] = ksum_r;
    else if (t < 192) g_svp[pbase * 64 + t - 128] = sv_r;
    else g_cvp[pbase * 64 + t - 192] = cv_r;
    if (t == 0) g_scp[pbase * 2 + 0] = ssum_r;
    if (t == 1) g_scp[pbase * 2 + 1] = csum_r;
}

// combine partials; also derive P1/P2/Q per head
__global__ __launch_bounds__(256) void kv_combine() {
    const int bh = blockIdx.x;
    const int t = threadIdx.x;

    __shared__ float kv_s[128 * 64];
    __shared__ float ksum_s[128];
    __shared__ float sv_s[64], cv_s[64];

    // sum kv partials: 32 elements per thread
#pragma unroll 4
    for (int e = t * 32; e < t * 32 + 32; e += 4) {
        float4 s = make_float4(0.f, 0.f, 0.f, 0.f);
#pragma unroll
        for (int p = 0; p < NSPLIT; p++) {
            const float4 v = *(const float4*)(g_kvp + (size_t)(p * NBH + bh) * 8192 + e);
            s.x += v.x; s.y += v.y; s.z += v.z; s.w += v.w;
        }
        *(float4*)(kv_s + e) = s;
        *(float4*)(g_kv + (size_t)bh * 8192 + e) = s;
    }
    if (t < 128) {
        float s = 0.f;
#pragma unroll
        for (int p = 0; p < NSPLIT; p++) s += g_ksump[(p * NBH + bh) * 128 + t];
        ksum_s[t] = s;
        g_ksum[bh * 128 + t] = s;
    } else if (t < 192) {
        float s = 0.f;
#pragma unroll
        for (int p = 0; p < NSPLIT; p++) s += g_svp[(p * NBH + bh) * 64 + t - 128];
        sv_s[t - 128] = s;
    } else {
        float s = 0.f;
#pragma unroll
        for (int p = 0; p < NSPLIT; p++) s += g_cvp[(p * NBH + bh) * 64 + t - 192];
        cv_s[t - 192] = s;
    }
    __syncthreads();

    if (t < 64) {
        float ks1 = 0.f;
#pragma unroll 8
        for (int i = 0; i < 64; i++) ks1 += kv_s[i * 64 + t];
        g_P1[bh * 64 + t] = 63.f * sv_s[t] - ks1;
    } else if (t < 128) {
        const int j = t - 64;
        float ks2 = 0.f;
#pragma unroll 8
        for (int i = 64; i < 128; i++) ks2 += kv_s[i * 64 + j];
        g_P2[bh * 64 + j] = 63.f * cv_s[j] - ks2;
    } else if (t == 128) {
        float s1k = 0.f;
        for (int i = 0; i < 64; i++) s1k += ksum_s[i];
        float ss = 0.f;
        for (int p = 0; p < NSPLIT; p++) ss += g_scp[(p * NBH + bh) * 2];
        g_Q[bh * 2] = 63.f * ss - s1k;
    } else if (t == 129) {
        float s2k = 0.f;
        for (int i = 64; i < 128; i++) s2k += ksum_s[i];
        float cc = 0.f;
        for (int p = 0; p < NSPLIT; p++) cc += g_scp[(p * NBH + bh) * 2 + 1];
        g_Q[bh * 2 + 1] = 63.f * cc - s2k;
    }
}

// ---------------- apply: out = (z1+z2)*qf@kv + z2*(sin*P1 + cos*P2) --------
__global__ __launch_bounds__(256) void attn_apply() {
    const int bh = blockIdx.x;
    const int b = bh / H_, h = bh % H_;
    const int lbase = blockIdx.y * 128;

    __shared__ float kv_s[128][64];
    __shared__ float ksum_s[128];
    __shared__ float P1_s[64], P2_s[64];
    __shared__ float qf_s[8][128];
    __shared__ float zz_s[8][2];

    const int t = threadIdx.x;
    const int w = t >> 5, lane = t & 31;

    const float* KVp = g_kv + (size_t)bh * 8192;
    for (int i = t; i < 2048; i += 256)
        *(float4*)(&kv_s[0][0] + i * 4) = *(const float4*)(KVp + i * 4);
    if (t < 128) ksum_s[t] = g_ksum[bh * 128 + t];
    else if (t < 192) P1_s[t - 128] = g_P1[bh * 64 + t - 128];
    else P2_s[t - 192] = g_P2[bh * 64 + t - 192];
    const float Q1 = g_Q[bh * 2], Q2 = g_Q[bh * 2 + 1];
    __syncthreads();

    const float* Qp = g_q + (size_t)b * L_ * E_ + h * D_;
    const float angk = PI_HALF / (float)L_;

    for (int lc = 0; lc < 128; lc += 8) {
        const int pos = lbase + lc + w;
        float sn, cs;
        __sincosf(angk * (float)(pos + 1), &sn, &cs);
        const size_t roff = (size_t)pos * E_;
        float q0 = Qp[roff + lane];
        float q1 = Qp[roff + lane + 32];
        float m = fmaxf(q0, q1);
#pragma unroll
        for (int o = 16; o; o >>= 1) m = fmaxf(m, __shfl_xor_sync(0xffffffffu, m, o));
        float e0 = __expf(q0 - m), e1 = __expf(q1 - m);
        float s = e0 + e1;
#pragma unroll
        for (int o = 16; o; o >>= 1) s += __shfl_xor_sync(0xffffffffu, s, o);
        float inv = 1.f / s;
        float s0 = e0 * inv, s1 = e1 * inv;
        float f0 = s0 * sn, f1 = s1 * sn, f2 = s0 * cs, f3 = s1 * cs;
        qf_s[w][lane]      = f0;  qf_s[w][lane + 32] = f1;
        qf_s[w][lane + 64] = f2;  qf_s[w][lane + 96] = f3;
        float d1 = f0 * ksum_s[lane] + f1 * ksum_s[lane + 32] +
                   f2 * ksum_s[lane + 64] + f3 * ksum_s[lane + 96];
#pragma unroll
        for (int o = 16; o; o >>= 1) d1 += __shfl_xor_sync(0xffffffffu, d1, o);
        if (lane == 0) {
            float z1 = 1.f / fmaxf(d1, 1e-6f);
            float d2 = sn * Q1 + cs * Q2 + d1;
            float z2 = 1.f / fmaxf(d2, 1e-6f);
            zz_s[w][0] = z1 + z2;
            zz_s[w][1] = z2;
        }
        __syncthreads();

        // phase 2: p = w, output pair d0 = lane*2; a1 only (comp folded out)
        const int p = w;
        const int d0 = lane * 2;
        float a1x = 0.f, a1y = 0.f;
#pragma unroll
        for (int i = 0; i < 128; i += 4) {
            float4 f4 = *(const float4*)&qf_s[p][i];
            float2 k0v = *(const float2*)&kv_s[i + 0][d0];
            float2 k1v = *(const float2*)&kv_s[i + 1][d0];
            float2 k2v = *(const float2*)&kv_s[i + 2][d0];
            float2 k3v = *(const float2*)&kv_s[i + 3][d0];
            a1x += f4.x * k0v.x; a1y += f4.x * k0v.y;
            a1x += f4.y * k1v.x; a1y += f4.y * k1v.y;
            a1x += f4.z * k2v.x; a1y += f4.z * k2v.y;
            a1x += f4.w * k3v.x; a1y += f4.w * k3v.y;
        }
        // recompute sn/cs for row p of this chunk
        float snp, csp;
        __sincosf(angk * (float)(lbase + lc + p + 1), &snp, &csp);
        const float zzsum = zz_s[p][0], z2 = zz_s[p][1];
        float o0 = zzsum * a1x + z2 * (snp * P1_s[d0] + csp * P2_s[d0]);
        float o1 = zzsum * a1y + z2 * (snp * P1_s[d0 + 1] + csp * P2_s[d0 + 1]);
        const int posl = lbase + lc + p;
        const size_t oidx = ((size_t)posl * B_ + b) * E_ + h * D_ + d0;
        __nv_bfloat16 h0, h1, l0v, l1v;
        split_bf16(o0, h0, l0v);
        split_bf16(o1, h1, l1v);
        *(__nv_bfloat162*)(g_ahi + oidx) = __nv_bfloat162(h0, h1);
        *(__nv_bfloat162*)(g_alo + oidx) = __nv_bfloat162(l0v, l1v);
        __syncthreads();
    }
}

// ---------------- launch ----------------------------------------------------
extern "C" void kernel_launch(void* const* d_in, const int* in_sizes, int n_in,
                              void* d_out, int out_size) {
    const float* X  = (const float*)d_in[0];
    const float* Wq = (const float*)d_in[1];
    const float* bq = (const float*)d_in[2];
    const float* Wk = (const float*)d_in[3];
    const float* bk = (const float*)d_in[4];
    const float* Wv = (const float*)d_in[5];
    const float* bv = (const float*)d_in[6];
    const float* Wo = (const float*)d_in[7];
    const float* bo = (const float*)d_in[8];
    float* out = (float*)d_out;

    cudaFuncSetAttribute(qkv_mma, cudaFuncAttributeMaxDynamicSharedMemorySize, DSMEM);
    cudaFuncSetAttribute(oproj_mma, cudaFuncAttributeMaxDynamicSharedMemorySize, DSMEM);

    convert_x<<<(M_ * E_) / (256 * 4), 256>>>(X);
    convert_w<<<dim3(32, 32, 4), dim3(32, 8)>>>(Wq, Wk, Wv, Wo);
    qkv_mma<<<dim3(8, 128, 3), 256, DSMEM>>>(bq, bk, bv);
    kv_reduce_part<<<dim3(NBH, NSPLIT), 256>>>();
    kv_combine<<<NBH, 256>>>();
    attn_apply<<<dim3(NBH, L_ / 128), 256>>>();
    oproj_mma<<<dim3(8, 128), 256, DSMEM>>>(bo, out);
}

// round 5
// speedup vs baseline: 2.1455x; 1.0936x over previous
#include <cuda_runtime.h>
#include <cuda_bf16.h>
#include <cstdint>

// Problem constants
#define B_  8
#define L_  2048
#define E_  1024
#define H_  16
#define D_  64
#define M_  (B_ * L_)        // 16384 rows
#define NBH (B_ * H_)        // 128 head-batches
#define NSPLIT 16
#define LSPL (L_ / NSPLIT)   // 128
#define PI_HALF 1.5707963267948966f

// ---------------- device scratch (no allocations allowed) ----------------
__device__ float g_q[(size_t)M_ * E_];
__device__ float g_k[(size_t)M_ * E_];
__device__ float g_v[(size_t)M_ * E_];
__device__ __nv_bfloat16 g_xhi[(size_t)M_ * E_];
__device__ __nv_bfloat16 g_xlo[(size_t)M_ * E_];
__device__ __nv_bfloat16 g_ahi[(size_t)M_ * E_];   // attn out hi (rows l*B+b)
__device__ __nv_bfloat16 g_alo[(size_t)M_ * E_];   // attn out lo
__device__ __nv_bfloat16 g_wthi[4ull * E_ * E_];   // W^T hi, per matrix [n][k]
__device__ __nv_bfloat16 g_wtlo[4ull * E_ * E_];
__device__ float g_ksum[NBH * 128];
__device__ float g_P1[NBH * 64];                   // 63*sv - KS1
__device__ float g_P2[NBH * 64];                   // 63*cv - KS2
__device__ float g_Q[NBH * 2];                     // 63*ssum-S1k, 63*csum-S2k
__device__ __nv_bfloat16 g_kvthi[(size_t)NBH * 64 * 128]; // kv^T [j][i] hi
__device__ __nv_bfloat16 g_kvtlo[(size_t)NBH * 64 * 128]; // kv^T lo
// split partials
__device__ float g_kvp[(size_t)NSPLIT * NBH * 128 * 64];
__device__ float g_ksump[NSPLIT * NBH * 128];
__device__ float g_svp[NSPLIT * NBH * 64];
__device__ float g_cvp[NSPLIT * NBH * 64];
__device__ float g_scp[NSPLIT * NBH * 2];

// ---------------- PTX helpers ----------------------------------------------
#define CP16(dst, src) \
    asm volatile("cp.async.cg.shared.global [%0], [%1], 16;" :: "r"(dst), "l"(src))

#define LDSM4(r, addr) \
    asm volatile("ldmatrix.sync.aligned.m8n8.x4.shared.b16 {%0,%1,%2,%3}, [%4];" \
                 : "=r"((r)[0]), "=r"((r)[1]), "=r"((r)[2]), "=r"((r)[3]) : "r"(addr))

#define MMA_BF16(d, a, b0, b1) \
    asm volatile("mma.sync.aligned.m16n8k16.row.col.f32.bf16.bf16.f32 " \
                 "{%0,%1,%2,%3},{%4,%5,%6,%7},{%8,%9},{%0,%1,%2,%3};" \
                 : "+f"((d)[0]), "+f"((d)[1]), "+f"((d)[2]), "+f"((d)[3]) \
                 : "r"((a)[0]), "r"((a)[1]), "r"((a)[2]), "r"((a)[3]), \
                   "r"(b0), "r"(b1))

// ---------------- conversions ----------------------------------------------
__device__ __forceinline__ void split_bf16(float v, __nv_bfloat16& h, __nv_bfloat16& l) {
    h = __float2bfloat16(v);
    l = __float2bfloat16(v - __bfloat162float(h));
}

__global__ __launch_bounds__(256) void convert_x(const float* __restrict__ X) {
    size_t i = ((size_t)blockIdx.x * 256 + threadIdx.x) * 4;
    float4 v = *(const float4*)(X + i);
    __nv_bfloat16 h0, h1, h2, h3, l0, l1, l2, l3;
    split_bf16(v.x, h0, l0); split_bf16(v.y, h1, l1);
    split_bf16(v.z, h2, l2); split_bf16(v.w, h3, l3);
    *(__nv_bfloat162*)(g_xhi + i)     = __nv_bfloat162(h0, h1);
    *(__nv_bfloat162*)(g_xhi + i + 2) = __nv_bfloat162(h2, h3);
    *(__nv_bfloat162*)(g_xlo + i)     = __nv_bfloat162(l0, l1);
    *(__nv_bfloat162*)(g_xlo + i + 2) = __nv_bfloat162(l2, l3);
}

// transpose + split: W[k][n] (fp32, n contiguous) -> WT[n][k] bf16 hi/lo
__global__ void convert_w(const float* __restrict__ Wq, const float* __restrict__ Wk,
                          const float* __restrict__ Wv, const float* __restrict__ Wo) {
    const float* W = (blockIdx.z == 0) ? Wq : (blockIdx.z == 1) ? Wk
                   : (blockIdx.z == 2) ? Wv : Wo;
    __shared__ float t[32][33];
    const int nb = blockIdx.x * 32, kb = blockIdx.y * 32;
    const int tx = threadIdx.x, ty = threadIdx.y;
#pragma unroll
    for (int i = 0; i < 4; i++)
        t[ty + 8 * i][tx] = W[(size_t)(kb + ty + 8 * i) * E_ + nb + tx];
    __syncthreads();
    __nv_bfloat16* Oh = g_wthi + (size_t)blockIdx.z * E_ * E_;
    __nv_bfloat16* Ol = g_wtlo + (size_t)blockIdx.z * E_ * E_;
#pragma unroll
    for (int i = 0; i < 4; i++) {
        int n = nb + ty + 8 * i, k = kb + tx;
        float v = t[tx][ty + 8 * i];
        __nv_bfloat16 h, l;
        split_bf16(v, h, l);
        Oh[(size_t)n * E_ + k] = h;
        Ol[(size_t)n * E_ + k] = l;
    }
}

// ---------------- HMMA GEMM: C[128m,128n] = A(hi,lo) @ B(hi,lo)^T + bias ---
#define BK 32
#define STAGES 3
#define TROW 80
#define TILE_BYTES (128 * TROW)
#define STAGE_BYTES (4 * TILE_BYTES)
#define DSMEM (STAGES * STAGE_BYTES)
#define NCHUNK 32

__device__ __forceinline__ void gemm_tile(
    const __nv_bfloat16* __restrict__ Ahi, const __nv_bfloat16* __restrict__ Alo,
    const __nv_bfloat16* __restrict__ Bhi, const __nv_bfloat16* __restrict__ Blo,
    const float* __restrict__ bias, float* __restrict__ C,
    int mBase, int nBase)
{
    extern __shared__ char smem[];
    const uint32_t sbase = (uint32_t)__cvta_generic_to_shared(smem);
    const int tid = threadIdx.x;
    const int lane = tid & 31, wid = tid >> 5;
    const int wm = wid & 3, wn = wid >> 2;

    const __nv_bfloat16* gp[8];
    uint32_t soff[8];
#pragma unroll
    for (int i = 0; i < 8; i++) {
        const int cid  = i * 256 + tid;
        const int tile = cid >> 9;
        const int ci   = cid & 511;
        const int row  = ci >> 2;
        const int ch   = ci & 3;
        const __nv_bfloat16* base = (tile == 0) ? Ahi : (tile == 1) ? Alo
                                   : (tile == 2) ? Bhi : Blo;
        const int grow = ((tile < 2) ? mBase : nBase) + row;
        gp[i]   = base + (size_t)grow * E_ + ch * 8;
        soff[i] = (uint32_t)(tile * TILE_BYTES + row * TROW + ch * 16);
    }

    float acc[2][8][4];
#pragma unroll
    for (int mt = 0; mt < 2; mt++)
#pragma unroll
        for (int nt = 0; nt < 8; nt++)
#pragma unroll
            for (int j = 0; j < 4; j++) acc[mt][nt][j] = 0.f;

#pragma unroll
    for (int c = 0; c < 2; c++) {
        const uint32_t sb = sbase + c * STAGE_BYTES;
#pragma unroll
        for (int i = 0; i < 8; i++) CP16(sb + soff[i], gp[i] + c * BK);
        asm volatile("cp.async.commit_group;" ::: "memory");
    }

    for (int c = 0; c < NCHUNK; c++) {
        asm volatile("cp.async.wait_group 1;" ::: "memory");
        __syncthreads();

        if (c + 2 < NCHUNK) {
            const uint32_t sb = sbase + (uint32_t)(((c + 2) % STAGES) * STAGE_BYTES);
            const size_t koff = (size_t)(c + 2) * BK;
#pragma unroll
            for (int i = 0; i < 8; i++) CP16(sb + soff[i], gp[i] + koff);
        }
        asm volatile("cp.async.commit_group;" ::: "memory");

        const uint32_t st = sbase + (uint32_t)((c % STAGES) * STAGE_BYTES);
#pragma unroll
        for (int ks = 0; ks < 2; ks++) {
            uint32_t ah[2][4], al[2][4], bh[4][4], bl[4][4];
#pragma unroll
            for (int mt = 0; mt < 2; mt++) {
                const uint32_t ad = st + (uint32_t)((wm * 32 + mt * 16 + (lane & 15)) * TROW
                                  + (ks * 2 + (lane >> 4)) * 16);
                LDSM4(ah[mt], ad);
                LDSM4(al[mt], ad + TILE_BYTES);
            }
#pragma unroll
            for (int nt = 0; nt < 4; nt++) {
                const uint32_t bd = st + 2 * TILE_BYTES
                                  + (uint32_t)((wn * 64 + nt * 16 + (lane & 15)) * TROW
                                  + (ks * 2 + (lane >> 4)) * 16);
                LDSM4(bh[nt], bd);
                LDSM4(bl[nt], bd + TILE_BYTES);
            }
#pragma unroll
            for (int mt = 0; mt < 2; mt++)
#pragma unroll
                for (int nt = 0; nt < 4; nt++) {
                    MMA_BF16(acc[mt][nt * 2],     ah[mt], bh[nt][0], bh[nt][2]);
                    MMA_BF16(acc[mt][nt * 2],     ah[mt], bl[nt][0], bl[nt][2]);
                    MMA_BF16(acc[mt][nt * 2],     al[mt], bh[nt][0], bh[nt][2]);
                    MMA_BF16(acc[mt][nt * 2 + 1], ah[mt], bh[nt][1], bh[nt][3]);
                    MMA_BF16(acc[mt][nt * 2 + 1], ah[mt], bl[nt][1], bl[nt][3]);
                    MMA_BF16(acc[mt][nt * 2 + 1], al[mt], bh[nt][1], bh[nt][3]);
                }
        }
    }

    const int r0 = lane >> 2, cq = (lane & 3) * 2;
#pragma unroll
    for (int mt = 0; mt < 2; mt++)
#pragma unroll
        for (int nt8 = 0; nt8 < 8; nt8++) {
            const int col = nBase + wn * 64 + nt8 * 8 + cq;
            const float2 bv = *(const float2*)(bias + col);
            const int row = mBase + wm * 32 + mt * 16 + r0;
            float* cp0 = C + (size_t)row * E_ + col;
            *(float2*)cp0 = make_float2(acc[mt][nt8][0] + bv.x, acc[mt][nt8][1] + bv.y);
            float* cp1 = cp0 + 8 * E_;
            *(float2*)cp1 = make_float2(acc[mt][nt8][2] + bv.x, acc[mt][nt8][3] + bv.y);
        }
}

__global__ __launch_bounds__(256, 1) void qkv_mma(const float* __restrict__ bq,
                                                  const float* __restrict__ bk,
                                                  const float* __restrict__ bv) {
    const int z = blockIdx.z;
    const float* bias = (z == 0) ? bq : (z == 1) ? bk : bv;
    float* C = (z == 0) ? g_q : (z == 1) ? g_k : g_v;
    gemm_tile(g_xhi, g_xlo,
              g_wthi + (size_t)z * E_ * E_, g_wtlo + (size_t)z * E_ * E_,
              bias, C, blockIdx.y * 128, blockIdx.x * 128);
}

__global__ __launch_bounds__(256, 1) void oproj_mma(const float* __restrict__ bo,
                                                    float* __restrict__ out) {
    gemm_tile(g_ahi, g_alo,
              g_wthi + 3ull * E_ * E_, g_wtlo + 3ull * E_ * E_,
              bo, out, blockIdx.y * 128, blockIdx.x * 128);
}

// ---------------- KV reduction (split over L) ------------------------------
__global__ __launch_bounds__(256) void kv_reduce_part() {
    const int bh = blockIdx.x;
    const int sp = blockIdx.y;
    const int b = bh / H_, h = bh % H_;
    const int pbase = sp * NBH + bh;

    __shared__ float kf_s[8][128];
    __shared__ float v_s[8][64];
    __shared__ float sins[8], coss[8];

    const int t = threadIdx.x;
    const int w = t >> 5, lane = t & 31;
    const int ti = t >> 4;
    const int tj = t & 15;

    float acc[8][4];
#pragma unroll
    for (int i = 0; i < 8; i++)
#pragma unroll
        for (int j = 0; j < 4; j++) acc[i][j] = 0.f;
    float ksum_r = 0.f, sv_r = 0.f, cv_r = 0.f, ssum_r = 0.f, csum_r = 0.f;

    const float* Kp = g_k + (size_t)b * L_ * E_ + h * D_;
    const float* Vp = g_v + (size_t)b * L_ * E_ + h * D_;
    const float angk = PI_HALF / (float)L_;

    for (int l = sp * LSPL; l < (sp + 1) * LSPL; l += 8) {
        const int pos = l + w;
        float sn, cs;
        __sincosf(angk * (float)(pos + 1), &sn, &cs);
        const size_t roff = (size_t)pos * E_;
        float k0 = Kp[roff + lane];
        float k1 = Kp[roff + lane + 32];
        float m = fmaxf(k0, k1);
#pragma unroll
        for (int o = 16; o; o >>= 1) m = fmaxf(m, __shfl_xor_sync(0xffffffffu, m, o));
        float e0 = __expf(k0 - m), e1 = __expf(k1 - m);
        float s = e0 + e1;
#pragma unroll
        for (int o = 16; o; o >>= 1) s += __shfl_xor_sync(0xffffffffu, s, o);
        float inv = 1.f / s;
        float s0 = e0 * inv, s1 = e1 * inv;
        kf_s[w][lane]      = s0 * sn;
        kf_s[w][lane + 32] = s1 * sn;
        kf_s[w][lane + 64] = s0 * cs;
        kf_s[w][lane + 96] = s1 * cs;
        v_s[w][lane]      = Vp[roff + lane];
        v_s[w][lane + 32] = Vp[roff + lane + 32];
        if (lane == 0) { sins[w] = sn; coss[w] = cs; }
        __syncthreads();

#pragma unroll
        for (int p = 0; p < 8; p++) {
            float4 vv = *(const float4*)&v_s[p][tj * 4];
#pragma unroll
            for (int ii = 0; ii < 8; ii++) {
                float kf = kf_s[p][ti * 8 + ii];
                acc[ii][0] += kf * vv.x;
                acc[ii][1] += kf * vv.y;
                acc[ii][2] += kf * vv.z;
                acc[ii][3] += kf * vv.w;
            }
        }
        if (t < 128) {
#pragma unroll
            for (int p = 0; p < 8; p++) ksum_r += kf_s[p][t];
        } else if (t < 192) {
#pragma unroll
            for (int p = 0; p < 8; p++) sv_r += sins[p] * v_s[p][t - 128];
        } else {
#pragma unroll
            for (int p = 0; p < 8; p++) cv_r += coss[p] * v_s[p][t - 192];
        }
        if (t == 0) {
#pragma unroll
            for (int p = 0; p < 8; p++) ssum_r += sins[p];
        }
        if (t == 1) {
#pragma unroll
            for (int p = 0; p < 8; p++) csum_r += csum_r * 0.f + coss[p];
        }
        __syncthreads();
    }

    float* KVp = g_kvp + (size_t)pbase * 8192;
#pragma unroll
    for (int ii = 0; ii < 8; ii++)
        *(float4*)(KVp + (ti * 8 + ii) * 64 + tj * 4) =
            make_float4(acc[ii][0], acc[ii][1], acc[ii][2], acc[ii][3]);
    if (t < 128) g_ksump[pbase * 128 + t] = ksum_r;
    else if (t < 192) g_svp[pbase * 64 + t - 128] = sv_r;
    else g_cvp[pbase * 64 + t - 192] = cv_r;
    if (t == 0) g_scp[pbase * 2 + 0] = ssum_r;
    if (t == 1) g_scp[pbase * 2 + 1] = csum_r;
}

// combine partials; derive P1/P2/Q; emit kv^T split-bf16 for the apply MMA
__global__ __launch_bounds__(256) void kv_combine() {
    const int bh = blockIdx.x;
    const int t = threadIdx.x;

    __shared__ float kv_s[128 * 64];
    __shared__ float ksum_s[128];
    __shared__ float sv_s[64], cv_s[64];

#pragma unroll 4
    for (int e = t * 32; e < t * 32 + 32; e += 4) {
        float4 s = make_float4(0.f, 0.f, 0.f, 0.f);
#pragma unroll
        for (int p = 0; p < NSPLIT; p++) {
            const float4 v = *(const float4*)(g_kvp + (size_t)(p * NBH + bh) * 8192 + e);
            s.x += v.x; s.y += v.y; s.z += v.z; s.w += v.w;
        }
        *(float4*)(kv_s + e) = s;
    }
    if (t < 128) {
        float s = 0.f;
#pragma unroll
        for (int p = 0; p < NSPLIT; p++) s += g_ksump[(p * NBH + bh) * 128 + t];
        ksum_s[t] = s;
        g_ksum[bh * 128 + t] = s;
    } else if (t < 192) {
        float s = 0.f;
#pragma unroll
        for (int p = 0; p < NSPLIT; p++) s += g_svp[(p * NBH + bh) * 64 + t - 128];
        sv_s[t - 128] = s;
    } else {
        float s = 0.f;
#pragma unroll
        for (int p = 0; p < NSPLIT; p++) s += g_cvp[(p * NBH + bh) * 64 + t - 192];
        cv_s[t - 192] = s;
    }
    __syncthreads();

    // kv^T split-bf16: [j][i], i contiguous
    {
        const int j = t & 63;
        const int i0 = (t >> 6) * 32;
        __nv_bfloat16* Oh = g_kvthi + (size_t)bh * 8192 + j * 128;
        __nv_bfloat16* Ol = g_kvtlo + (size_t)bh * 8192 + j * 128;
#pragma unroll 4
        for (int i = i0; i < i0 + 32; i += 2) {
            float a = kv_s[i * 64 + j];
            float c = kv_s[(i + 1) * 64 + j];
            __nv_bfloat16 ah, al, ch, cl;
            split_bf16(a, ah, al);
            split_bf16(c, ch, cl);
            *(__nv_bfloat162*)(Oh + i) = __nv_bfloat162(ah, ch);
            *(__nv_bfloat162*)(Ol + i) = __nv_bfloat162(al, cl);
        }
    }

    if (t < 64) {
        float ks1 = 0.f;
#pragma unroll 8
        for (int i = 0; i < 64; i++) ks1 += kv_s[i * 64 + t];
        g_P1[bh * 64 + t] = 63.f * sv_s[t] - ks1;
    } else if (t < 128) {
        const int j = t - 64;
        float ks2 = 0.f;
#pragma unroll 8
        for (int i = 64; i < 128; i++) ks2 += kv_s[i * 64 + j];
        g_P2[bh * 64 + j] = 63.f * cv_s[j] - ks2;
    } else if (t == 128) {
        float s1k = 0.f;
        for (int i = 0; i < 64; i++) s1k += ksum_s[i];
        float ss = 0.f;
        for (int p = 0; p < NSPLIT; p++) ss += g_scp[(p * NBH + bh) * 2];
        g_Q[bh * 2] = 63.f * ss - s1k;
    } else if (t == 129) {
        float s2k = 0.f;
        for (int i = 64; i < 128; i++) s2k += ksum_s[i];
        float cc = 0.f;
        for (int p = 0; p < NSPLIT; p++) cc += g_scp[(p * NBH + bh) * 2 + 1];
        g_Q[bh * 2 + 1] = 63.f * cc - s2k;
    }
}

// ---------------- apply via HMMA: C = qf @ kv^T, then normalize ------------
// smem layout (dynamic):
#define AROW 272                 // 128 bf16 + 8 pad -> 272B row stride
#define OFF_QFHI 0
#define OFF_QFLO (128 * AROW)                 // 34816
#define OFF_KTHI (2 * 128 * AROW)             // 69632
#define OFF_KTLO (2 * 128 * AROW + 64 * AROW) // 87040
#define OFF_KSUM (2 * 128 * AROW + 2 * 64 * AROW)  // 104448
#define OFF_P1   (OFF_KSUM + 512)
#define OFF_P2   (OFF_P1 + 256)
#define OFF_ZZ   (OFF_P2 + 256)
#define OFF_Z2   (OFF_ZZ + 512)
#define OFF_SN   (OFF_Z2 + 512)
#define OFF_CS   (OFF_SN + 512)
#define ATTN_SMEM (OFF_CS + 512)              // 107520

__global__ __launch_bounds__(256) void attn_apply() {
    extern __shared__ char sm[];
    const uint32_t sbase = (uint32_t)__cvta_generic_to_shared(sm);
    const int bh = blockIdx.x;
    const int b = bh / H_, h = bh % H_;
    const int lbase = blockIdx.y * 128;
    const int t = threadIdx.x;
    const int w = t >> 5, lane = t & 31;

    float* ksum_s = (float*)(sm + OFF_KSUM);
    float* P1_s   = (float*)(sm + OFF_P1);
    float* P2_s   = (float*)(sm + OFF_P2);
    float* zz_s   = (float*)(sm + OFF_ZZ);
    float* z2_s   = (float*)(sm + OFF_Z2);
    float* sn_s   = (float*)(sm + OFF_SN);
    float* cs_s   = (float*)(sm + OFF_CS);

    // load kv^T tiles (16KB each) + ksum/P1/P2
    {
        const __nv_bfloat16* Gh = g_kvthi + (size_t)bh * 8192;
        const __nv_bfloat16* Gl = g_kvtlo + (size_t)bh * 8192;
#pragma unroll
        for (int c = t; c < 1024; c += 256) {
            const int row = c >> 4, ch = c & 15;
            const uint32_t off = row * AROW + ch * 16;
            *(uint4*)(sm + OFF_KTHI + off) = *(const uint4*)(Gh + c * 8);
            *(uint4*)(sm + OFF_KTLO + off) = *(const uint4*)(Gl + c * 8);
        }
        if (t < 128) ksum_s[t] = g_ksum[bh * 128 + t];
        else if (t < 192) P1_s[t - 128] = g_P1[bh * 64 + t - 128];
        else P2_s[t - 192] = g_P2[bh * 64 + t - 192];
    }
    const float Q1 = g_Q[bh * 2], Q2 = g_Q[bh * 2 + 1];
    __syncthreads();

    // softmax + qf build: warp w handles rows w*16 .. w*16+15
    const float* Qp = g_q + (size_t)b * L_ * E_ + h * D_;
    const float angk = PI_HALF / (float)L_;
    __nv_bfloat16* qfhi = (__nv_bfloat16*)(sm + OFF_QFHI);
    __nv_bfloat16* qflo = (__nv_bfloat16*)(sm + OFF_QFLO);

    for (int r = 0; r < 16; r++) {
        const int row = w * 16 + r;
        const int pos = lbase + row;
        float sn, cs;
        __sincosf(angk * (float)(pos + 1), &sn, &cs);
        const size_t roff = (size_t)pos * E_;
        float q0 = Qp[roff + lane];
        float q1 = Qp[roff + lane + 32];
        float m = fmaxf(q0, q1);
#pragma unroll
        for (int o = 16; o; o >>= 1) m = fmaxf(m, __shfl_xor_sync(0xffffffffu, m, o));
        float e0 = __expf(q0 - m), e1 = __expf(q1 - m);
        float s = e0 + e1;
#pragma unroll
        for (int o = 16; o; o >>= 1) s += __shfl_xor_sync(0xffffffffu, s, o);
        float inv = 1.f / s;
        float s0 = e0 * inv, s1 = e1 * inv;
        float f0 = s0 * sn, f1 = s1 * sn, f2 = s0 * cs, f3 = s1 * cs;
        __nv_bfloat16 hh, ll;
        const int rb = row * 136;   // elements (AROW/2)
        split_bf16(f0, hh, ll); qfhi[rb + lane] = hh;      qflo[rb + lane] = ll;
        split_bf16(f1, hh, ll); qfhi[rb + lane + 32] = hh; qflo[rb + lane + 32] = ll;
        split_bf16(f2, hh, ll); qfhi[rb + lane + 64] = hh; qflo[rb + lane + 64] = ll;
        split_bf16(f3, hh, ll); qfhi[rb + lane + 96] = hh; qflo[rb + lane + 96] = ll;
        float d1 = f0 * ksum_s[lane] + f1 * ksum_s[lane + 32] +
                   f2 * ksum_s[lane + 64] + f3 * ksum_s[lane + 96];
#pragma unroll
        for (int o = 16; o; o >>= 1) d1 += __shfl_xor_sync(0xffffffffu, d1, o);
        if (lane == 0) {
            float z1 = 1.f / fmaxf(d1, 1e-6f);
            float d2 = sn * Q1 + cs * Q2 + d1;
            float z2 = 1.f / fmaxf(d2, 1e-6f);
            zz_s[row] = z1 + z2;
            z2_s[row] = z2;
            sn_s[row] = sn;
            cs_s[row] = cs;
        }
    }
    __syncthreads();

    // MMA: warp w -> rows m0=w*16 (m16), all 64 cols, K=128
    const int m0 = w * 16;
    float acc[8][4];
#pragma unroll
    for (int nt = 0; nt < 8; nt++)
#pragma unroll
        for (int j = 0; j < 4; j++) acc[nt][j] = 0.f;

    const uint32_t aoffB = sbase + (uint32_t)((m0 + (lane & 15)) * AROW + (lane >> 4) * 16);
    const uint32_t boffB = sbase + (uint32_t)(((lane & 15)) * AROW + (lane >> 4) * 16);
#pragma unroll
    for (int ks = 0; ks < 8; ks++) {
        uint32_t aH[4], aL[4], bH[4][4], bL[4][4];
        const uint32_t ao = aoffB + ks * 32;
        LDSM4(aH, ao + OFF_QFHI);
        LDSM4(aL, ao + OFF_QFLO);
#pragma unroll
        for (int nt = 0; nt < 4; nt++) {
            const uint32_t bo = boffB + nt * 16 * AROW + ks * 32;
            LDSM4(bH[nt], bo + OFF_KTHI);
            LDSM4(bL[nt], bo + OFF_KTLO);
        }
#pragma unroll
        for (int nt = 0; nt < 4; nt++) {
            MMA_BF16(acc[nt * 2],     aH, bH[nt][0], bH[nt][2]);
            MMA_BF16(acc[nt * 2],     aH, bL[nt][0], bL[nt][2]);
            MMA_BF16(acc[nt * 2],     aL, bH[nt][0], bH[nt][2]);
            MMA_BF16(acc[nt * 2 + 1], aH, bH[nt][1], bH[nt][3]);
            MMA_BF16(acc[nt * 2 + 1], aH, bL[nt][1], bL[nt][3]);
            MMA_BF16(acc[nt * 2 + 1], aL, bH[nt][1], bH[nt][3]);
        }
    }

    // epilogue: o = zz[row]*acc + z2[row]*(sn*P1[j] + cs*P2[j])
    const int r0 = lane >> 2, cq = (lane & 3) * 2;
#pragma unroll
    for (int nt8 = 0; nt8 < 8; nt8++) {
        const int j = nt8 * 8 + cq;
        const float p1x = P1_s[j], p1y = P1_s[j + 1];
        const float p2x = P2_s[j], p2y = P2_s[j + 1];
#pragma unroll
        for (int half = 0; half < 2; half++) {
            const int row = m0 + r0 + half * 8;
            const float oz = zz_s[row], o2 = z2_s[row];
            const float sr = sn_s[row], cr = cs_s[row];
            const float px = sr * p1x + cr * p2x;
            const float py = sr * p1y + cr * p2y;
            float o0 = oz * acc[nt8][half * 2 + 0] + o2 * px;
            float o1 = oz * acc[nt8][half * 2 + 1] + o2 * py;
            const int posl = lbase + row;
            const size_t oidx = ((size_t)posl * B_ + b) * E_ + h * D_ + j;
            __nv_bfloat16 h0, h1, l0v, l1v;
            split_bf16(o0, h0, l0v);
            split_bf16(o1, h1, l1v);
            *(__nv_bfloat162*)(g_ahi + oidx) = __nv_bfloat162(h0, h1);
            *(__nv_bfloat162*)(g_alo + oidx) = __nv_bfloat162(l0v, l1v);
        }
    }
}

// ---------------- launch ----------------------------------------------------
extern "C" void kernel_launch(void* const* d_in, const int* in_sizes, int n_in,
                              void* d_out, int out_size) {
    const float* X  = (const float*)d_in[0];
    const float* Wq = (const float*)d_in[1];
    const float* bq = (const float*)d_in[2];
    const float* Wk = (const float*)d_in[3];
    const float* bk = (const float*)d_in[4];
    const float* Wv = (const float*)d_in[5];
    const float* bv = (const float*)d_in[6];
    const float* Wo = (const float*)d_in[7];
    const float* bo = (const float*)d_in[8];
    float* out = (float*)d_out;

    cudaFuncSetAttribute(qkv_mma, cudaFuncAttributeMaxDynamicSharedMemorySize, DSMEM);
    cudaFuncSetAttribute(oproj_mma, cudaFuncAttributeMaxDynamicSharedMemorySize, DSMEM);
    cudaFuncSetAttribute(attn_apply, cudaFuncAttributeMaxDynamicSharedMemorySize, ATTN_SMEM);

    convert_x<<<(M_ * E_) / (256 * 4), 256>>>(X);
    convert_w<<<dim3(32, 32, 4), dim3(32, 8)>>>(Wq, Wk, Wv, Wo);
    qkv_mma<<<dim3(8, 128, 3), 256, DSMEM>>>(bq, bk, bv);
    kv_reduce_part<<<dim3(NBH, NSPLIT), 256>>>();
    kv_combine<<<NBH, 256>>>();
    attn_apply<<<dim3(NBH, L_ / 128), 256, ATTN_SMEM>>>();
    oproj_mma<<<dim3(8, 128), 256, DSMEM>>>(bo, out);
}

// round 7
// speedup vs baseline: 4.4084x; 2.0547x over previous
#include <cuda_runtime.h>
#include <cuda_bf16.h>
#include <cuda_fp16.h>
#include <cstdint>

// Problem constants
#define B_  8
#define L_  2048
#define E_  1024
#define H_  16
#define D_  64
#define M_  (B_ * L_)        // 16384 rows
#define NBH (B_ * H_)        // 128 head-batches
#define NSPLIT 16
#define LSPL (L_ / NSPLIT)   // 128
#define PI_HALF 1.5707963267948966f

// ---------------- device scratch (no allocations allowed) ----------------
__device__ float g_q[(size_t)M_ * E_];
__device__ float g_k[(size_t)M_ * E_];
__device__ float g_v[(size_t)M_ * E_];
__device__ __half g_xf[(size_t)M_ * E_];           // X fp16
__device__ __half g_af[(size_t)M_ * E_];           // attn out fp16 (rows l*B+b)
__device__ __half g_wtf[4ull * E_ * E_];           // W^T fp16, per matrix [n][k]
__device__ float g_ksum[NBH * 128];
__device__ float g_P1[NBH * 64];                   // 63*sv - KS1
__device__ float g_P2[NBH * 64];                   // 63*cv - KS2
__device__ float g_Q[NBH * 2];                     // 63*ssum-S1k, 63*csum-S2k
__device__ __nv_bfloat16 g_kvthi[(size_t)NBH * 64 * 128]; // kv^T [j][i] hi
__device__ __nv_bfloat16 g_kvtlo[(size_t)NBH * 64 * 128]; // kv^T lo
// split partials
__device__ float g_kvp[(size_t)NSPLIT * NBH * 128 * 64];
__device__ float g_ksump[NSPLIT * NBH * 128];
__device__ float g_svp[NSPLIT * NBH * 64];
__device__ float g_cvp[NSPLIT * NBH * 64];
__device__ float g_scp[NSPLIT * NBH * 2];

// ---------------- PTX helpers ----------------------------------------------
#define CP16(dst, src) \
    asm volatile("cp.async.cg.shared.global [%0], [%1], 16;" :: "r"(dst), "l"(src))

#define LDSM4(r, addr) \
    asm volatile("ldmatrix.sync.aligned.m8n8.x4.shared.b16 {%0,%1,%2,%3}, [%4];" \
                 : "=r"((r)[0]), "=r"((r)[1]), "=r"((r)[2]), "=r"((r)[3]) : "r"(addr))

#define MMA_F16(d, a, b0, b1) \
    asm volatile("mma.sync.aligned.m16n8k16.row.col.f32.f16.f16.f32 " \
                 "{%0,%1,%2,%3},{%4,%5,%6,%7},{%8,%9},{%0,%1,%2,%3};" \
                 : "+f"((d)[0]), "+f"((d)[1]), "+f"((d)[2]), "+f"((d)[3]) \
                 : "r"((a)[0]), "r"((a)[1]), "r"((a)[2]), "r"((a)[3]), \
                   "r"(b0), "r"(b1))

#define MMA_BF16(d, a, b0, b1) \
    asm volatile("mma.sync.aligned.m16n8k16.row.col.f32.bf16.bf16.f32 " \
                 "{%0,%1,%2,%3},{%4,%5,%6,%7},{%8,%9},{%0,%1,%2,%3};" \
                 : "+f"((d)[0]), "+f"((d)[1]), "+f"((d)[2]), "+f"((d)[3]) \
                 : "r"((a)[0]), "r"((a)[1]), "r"((a)[2]), "r"((a)[3]), \
                   "r"(b0), "r"(b1))

// ---------------- conversions ----------------------------------------------
__device__ __forceinline__ void split_bf16(float v, __nv_bfloat16& h, __nv_bfloat16& l) {
    h = __float2bfloat16(v);
    l = __float2bfloat16(v - __bfloat162float(h));
}

__global__ __launch_bounds__(256) void convert_x(const float* __restrict__ X) {
    size_t i = ((size_t)blockIdx.x * 256 + threadIdx.x) * 4;
    float4 v = *(const float4*)(X + i);
    *(__half2*)(g_xf + i)     = __floats2half2_rn(v.x, v.y);
    *(__half2*)(g_xf + i + 2) = __floats2half2_rn(v.z, v.w);
}

// transpose: W[k][n] (fp32, n contiguous) -> WT[n][k] fp16
__global__ void convert_w(const float* __restrict__ Wq, const float* __restrict__ Wk,
                          const float* __restrict__ Wv, const float* __restrict__ Wo) {
    const float* W = (blockIdx.z == 0) ? Wq : (blockIdx.z == 1) ? Wk
                   : (blockIdx.z == 2) ? Wv : Wo;
    __shared__ float t[32][33];
    const int nb = blockIdx.x * 32, kb = blockIdx.y * 32;
    const int tx = threadIdx.x, ty = threadIdx.y;
#pragma unroll
    for (int i = 0; i < 4; i++)
        t[ty + 8 * i][tx] = W[(size_t)(kb + ty + 8 * i) * E_ + nb + tx];
    __syncthreads();
    __half* Of = g_wtf + (size_t)blockIdx.z * E_ * E_;
#pragma unroll
    for (int i = 0; i < 4; i++) {
        int n = nb + ty + 8 * i, k = kb + tx;
        Of[(size_t)n * E_ + k] = __float2half(t[tx][ty + 8 * i]);
    }
}

// ---------------- fp16 HMMA GEMM: C[128m,128n] = A @ B^T + bias ------------
#define BK 32
#define STAGES 3
#define TROW 80
#define TILE_BYTES (128 * TROW)        // 10240
#define STAGE_BYTES (2 * TILE_BYTES)   // A, B = 20480
#define DSMEM (STAGES * STAGE_BYTES)   // 61440
#define NCHUNK 32

__device__ __forceinline__ void gemm_tile(
    const __half* __restrict__ A, const __half* __restrict__ Bm,
    const float* __restrict__ bias, float* __restrict__ C,
    int mBase, int nBase)
{
    extern __shared__ char smem[];
    const uint32_t sbase = (uint32_t)__cvta_generic_to_shared(smem);
    const int tid = threadIdx.x;
    const int lane = tid & 31, wid = tid >> 5;
    const int wm = wid & 3, wn = wid >> 2;   // warp tile: 32m x 64n

    // load mapping: 4 x 16B chunks per thread per stage (2 tiles of 128x32 fp16)
    const __half* gp[4];
    uint32_t soff[4];
#pragma unroll
    for (int i = 0; i < 4; i++) {
        const int cid  = i * 256 + tid;
        const int tile = cid >> 9;         // 0..1
        const int ci   = cid & 511;
        const int row  = ci >> 2;
        const int ch   = ci & 3;
        const __half* base = (tile == 0) ? A : Bm;
        const int grow = ((tile == 0) ? mBase : nBase) + row;
        gp[i]   = base + (size_t)grow * E_ + ch * 8;
        soff[i] = (uint32_t)(tile * TILE_BYTES + row * TROW + ch * 16);
    }

    float acc[2][8][4];
#pragma unroll
    for (int mt = 0; mt < 2; mt++)
#pragma unroll
        for (int nt = 0; nt < 8; nt++)
#pragma unroll
            for (int j = 0; j < 4; j++) acc[mt][nt][j] = 0.f;

#pragma unroll
    for (int c = 0; c < 2; c++) {
        const uint32_t sb = sbase + c * STAGE_BYTES;
#pragma unroll
        for (int i = 0; i < 4; i++) CP16(sb + soff[i], gp[i] + c * BK);
        asm volatile("cp.async.commit_group;" ::: "memory");
    }

    for (int c = 0; c < NCHUNK; c++) {
        asm volatile("cp.async.wait_group 1;" ::: "memory");
        __syncthreads();

        if (c + 2 < NCHUNK) {
            const uint32_t sb = sbase + (uint32_t)(((c + 2) % STAGES) * STAGE_BYTES);
            const size_t koff = (size_t)(c + 2) * BK;
#pragma unroll
            for (int i = 0; i < 4; i++) CP16(sb + soff[i], gp[i] + koff);
        }
        asm volatile("cp.async.commit_group;" ::: "memory");

        const uint32_t st = sbase + (uint32_t)((c % STAGES) * STAGE_BYTES);
#pragma unroll
        for (int ks = 0; ks < 2; ks++) {
            uint32_t a[2][4], b[4][4];
#pragma unroll
            for (int mt = 0; mt < 2; mt++) {
                const uint32_t ad = st + (uint32_t)((wm * 32 + mt * 16 + (lane & 15)) * TROW
                                  + (ks * 2 + (lane >> 4)) * 16);
                LDSM4(a[mt], ad);
            }
#pragma unroll
            for (int nt = 0; nt < 4; nt++) {
                const uint32_t bd = st + TILE_BYTES
                                  + (uint32_t)((wn * 64 + nt * 16 + (lane & 15)) * TROW
                                  + (ks * 2 + (lane >> 4)) * 16);
                LDSM4(b[nt], bd);
            }
#pragma unroll
            for (int mt = 0; mt < 2; mt++)
#pragma unroll
                for (int nt = 0; nt < 4; nt++) {
                    MMA_F16(acc[mt][nt * 2],     a[mt], b[nt][0], b[nt][2]);
                    MMA_F16(acc[mt][nt * 2 + 1], a[mt], b[nt][1], b[nt][3]);
                }
        }
    }

    const int r0 = lane >> 2, cq = (lane & 3) * 2;
#pragma unroll
    for (int mt = 0; mt < 2; mt++)
#pragma unroll
        for (int nt8 = 0; nt8 < 8; nt8++) {
            const int col = nBase + wn * 64 + nt8 * 8 + cq;
            const float2 bv = *(const float2*)(bias + col);
            const int row = mBase + wm * 32 + mt * 16 + r0;
            float* cp0 = C + (size_t)row * E_ + col;
            *(float2*)cp0 = make_float2(acc[mt][nt8][0] + bv.x, acc[mt][nt8][1] + bv.y);
            float* cp1 = cp0 + 8 * E_;
            *(float2*)cp1 = make_float2(acc[mt][nt8][2] + bv.x, acc[mt][nt8][3] + bv.y);
        }
}

__global__ __launch_bounds__(256, 2) void qkv_mma(const float* __restrict__ bq,
                                                  const float* __restrict__ bk,
                                                  const float* __restrict__ bv) {
    const int z = blockIdx.z;
    const float* bias = (z == 0) ? bq : (z == 1) ? bk : bv;
    float* C = (z == 0) ? g_q : (z == 1) ? g_k : g_v;
    gemm_tile(g_xf, g_wtf + (size_t)z * E_ * E_,
              bias, C, blockIdx.y * 128, blockIdx.x * 128);
}

__global__ __launch_bounds__(256, 2) void oproj_mma(const float* __restrict__ bo,
                                                    float* __restrict__ out) {
    gemm_tile(g_af, g_wtf + 3ull * E_ * E_,
              bo, out, blockIdx.y * 128, blockIdx.x * 128);
}

// ---------------- KV reduction (split over L) ------------------------------
__global__ __launch_bounds__(256) void kv_reduce_part() {
    const int bh = blockIdx.x;
    const int sp = blockIdx.y;
    const int b = bh / H_, h = bh % H_;
    const int pbase = sp * NBH + bh;

    __shared__ float kf_s[8][128];
    __shared__ float v_s[8][64];
    __shared__ float sins[8], coss[8];

    const int t = threadIdx.x;
    const int w = t >> 5, lane = t & 31;
    const int ti = t >> 4;
    const int tj = t & 15;

    float acc[8][4];
#pragma unroll
    for (int i = 0; i < 8; i++)
#pragma unroll
        for (int j = 0; j < 4; j++) acc[i][j] = 0.f;
    float ksum_r = 0.f, sv_r = 0.f, cv_r = 0.f, ssum_r = 0.f, csum_r = 0.f;

    const float* Kp = g_k + (size_t)b * L_ * E_ + h * D_;
    const float* Vp = g_v + (size_t)b * L_ * E_ + h * D_;
    const float angk = PI_HALF / (float)L_;

    for (int l = sp * LSPL; l < (sp + 1) * LSPL; l += 8) {
        const int pos = l + w;
        float sn, cs;
        __sincosf(angk * (float)(pos + 1), &sn, &cs);
        const size_t roff = (size_t)pos * E_;
        float k0 = Kp[roff + lane];
        float k1 = Kp[roff + lane + 32];
        float m = fmaxf(k0, k1);
#pragma unroll
        for (int o = 16; o; o >>= 1) m = fmaxf(m, __shfl_xor_sync(0xffffffffu, m, o));
        float e0 = __expf(k0 - m), e1 = __expf(k1 - m);
        float s = e0 + e1;
#pragma unroll
        for (int o = 16; o; o >>= 1) s += __shfl_xor_sync(0xffffffffu, s, o);
        float inv = 1.f / s;
        float s0 = e0 * inv, s1 = e1 * inv;
        kf_s[w][lane]      = s0 * sn;
        kf_s[w][lane + 32] = s1 * sn;
        kf_s[w][lane + 64] = s0 * cs;
        kf_s[w][lane + 96] = s1 * cs;
        v_s[w][lane]      = Vp[roff + lane];
        v_s[w][lane + 32] = Vp[roff + lane + 32];
        if (lane == 0) { sins[w] = sn; coss[w] = cs; }
        __syncthreads();

#pragma unroll
        for (int p = 0; p < 8; p++) {
            float4 vv = *(const float4*)&v_s[p][tj * 4];
#pragma unroll
            for (int ii = 0; ii < 8; ii++) {
                float kf = kf_s[p][ti * 8 + ii];
                acc[ii][0] += kf * vv.x;
                acc[ii][1] += kf * vv.y;
                acc[ii][2] += kf * vv.z;
                acc[ii][3] += kf * vv.w;
            }
        }
        if (t < 128) {
#pragma unroll
            for (int p = 0; p < 8; p++) ksum_r += kf_s[p][t];
        } else if (t < 192) {
#pragma unroll
            for (int p = 0; p < 8; p++) sv_r += sins[p] * v_s[p][t - 128];
        } else {
#pragma unroll
            for (int p = 0; p < 8; p++) cv_r += coss[p] * v_s[p][t - 192];
        }
        if (t == 0) {
#pragma unroll
            for (int p = 0; p < 8; p++) ssum_r += sins[p];
        }
        if (t == 1) {
#pragma unroll
            for (int p = 0; p < 8; p++) csum_r += coss[p];
        }
        __syncthreads();
    }

    float* KVp = g_kvp + (size_t)pbase * 8192;
#pragma unroll
    for (int ii = 0; ii < 8; ii++)
        *(float4*)(KVp + (ti * 8 + ii) * 64 + tj * 4) =
            make_float4(acc[ii][0], acc[ii][1], acc[ii][2], acc[ii][3]);
    if (t < 128) g_ksump[pbase * 128 + t] = ksum_r;
    else if (t < 192) g_svp[pbase * 64 + t - 128] = sv_r;
    else g_cvp[pbase * 64 + t - 192] = cv_r;
    if (t == 0) g_scp[pbase * 2 + 0] = ssum_r;
    if (t == 1) g_scp[pbase * 2 + 1] = csum_r;
}

// combine partials; derive P1/P2/Q; emit kv^T split-bf16 for the apply MMA
__global__ __launch_bounds__(256) void kv_combine() {
    const int bh = blockIdx.x;
    const int t = threadIdx.x;

    __shared__ float kv_s[128 * 64];
    __shared__ float ksum_s[128];
    __shared__ float sv_s[64], cv_s[64];

#pragma unroll 4
    for (int e = t * 32; e < t * 32 + 32; e += 4) {
        float4 s = make_float4(0.f, 0.f, 0.f, 0.f);
#pragma unroll
        for (int p = 0; p < NSPLIT; p++) {
            const float4 v = *(const float4*)(g_kvp + (size_t)(p * NBH + bh) * 8192 + e);
            s.x += v.x; s.y += v.y; s.z += v.z; s.w += v.w;
        }
        *(float4*)(kv_s + e) = s;
    }
    if (t < 128) {
        float s = 0.f;
#pragma unroll
        for (int p = 0; p < NSPLIT; p++) s += g_ksump[(p * NBH + bh) * 128 + t];
        ksum_s[t] = s;
        g_ksum[bh * 128 + t] = s;
    } else if (t < 192) {
        float s = 0.f;
#pragma unroll
        for (int p = 0; p < NSPLIT; p++) s += g_svp[(p * NBH + bh) * 64 + t - 128];
        sv_s[t - 128] = s;
    } else {
        float s = 0.f;
#pragma unroll
        for (int p = 0; p < NSPLIT; p++) s += g_cvp[(p * NBH + bh) * 64 + t - 192];
        cv_s[t - 192] = s;
    }
    __syncthreads();

    // kv^T split-bf16: [j][i], i contiguous
    {
        const int j = t & 63;
        const int i0 = (t >> 6) * 32;
        __nv_bfloat16* Oh = g_kvthi + (size_t)bh * 8192 + j * 128;
        __nv_bfloat16* Ol = g_kvtlo + (size_t)bh * 8192 + j * 128;
#pragma unroll 4
        for (int i = i0; i < i0 + 32; i += 2) {
            float a = kv_s[i * 64 + j];
            float c = kv_s[(i + 1) * 64 + j];
            __nv_bfloat16 ah, al, ch, cl;
            split_bf16(a, ah, al);
            split_bf16(c, ch, cl);
            *(__nv_bfloat162*)(Oh + i) = __nv_bfloat162(ah, ch);
            *(__nv_bfloat162*)(Ol + i) = __nv_bfloat162(al, cl);
        }
    }

    if (t < 64) {
        float ks1 = 0.f;
#pragma unroll 8
        for (int i = 0; i < 64; i++) ks1 += kv_s[i * 64 + t];
        g_P1[bh * 64 + t] = 63.f * sv_s[t] - ks1;
    } else if (t < 128) {
        const int j = t - 64;
        float ks2 = 0.f;
#pragma unroll 8
        for (int i = 64; i < 128; i++) ks2 += kv_s[i * 64 + j];
        g_P2[bh * 64 + j] = 63.f * cv_s[j] - ks2;
    } else if (t == 128) {
        float s1k = 0.f;
        for (int i = 0; i < 64; i++) s1k += ksum_s[i];
        float ss = 0.f;
        for (int p = 0; p < NSPLIT; p++) ss += g_scp[(p * NBH + bh) * 2];
        g_Q[bh * 2] = 63.f * ss - s1k;
    } else if (t == 129) {
        float s2k = 0.f;
        for (int i = 64; i < 128; i++) s2k += ksum_s[i];
        float cc = 0.f;
        for (int p = 0; p < NSPLIT; p++) cc += g_scp[(p * NBH + bh) * 2 + 1];
        g_Q[bh * 2 + 1] = 63.f * cc - s2k;
    }
}

// ---------------- apply via HMMA: C = qf @ kv^T, then normalize ------------
#define AROW 272
#define OFF_QFHI 0
#define OFF_QFLO (128 * AROW)
#define OFF_KTHI (2 * 128 * AROW)
#define OFF_KTLO (2 * 128 * AROW + 64 * AROW)
#define OFF_KSUM (2 * 128 * AROW + 2 * 64 * AROW)
#define OFF_P1   (OFF_KSUM + 512)
#define OFF_P2   (OFF_P1 + 256)
#define OFF_ZZ   (OFF_P2 + 256)
#define OFF_Z2   (OFF_ZZ + 512)
#define OFF_SN   (OFF_Z2 + 512)
#define OFF_CS   (OFF_SN + 512)
#define ATTN_SMEM (OFF_CS + 512)

__global__ __launch_bounds__(256) void attn_apply() {
    extern __shared__ char sm[];
    const uint32_t sbase = (uint32_t)__cvta_generic_to_shared(sm);
    const int bh = blockIdx.x;
    const int b = bh / H_, h = bh % H_;
    const int lbase = blockIdx.y * 128;
    const int t = threadIdx.x;
    const int w = t >> 5, lane = t & 31;

    float* ksum_s = (float*)(sm + OFF_KSUM);
    float* P1_s   = (float*)(sm + OFF_P1);
    float* P2_s   = (float*)(sm + OFF_P2);
    float* zz_s   = (float*)(sm + OFF_ZZ);
    float* z2_s   = (float*)(sm + OFF_Z2);
    float* sn_s   = (float*)(sm + OFF_SN);
    float* cs_s   = (float*)(sm + OFF_CS);

    {
        const __nv_bfloat16* Gh = g_kvthi + (size_t)bh * 8192;
        const __nv_bfloat16* Gl = g_kvtlo + (size_t)bh * 8192;
#pragma unroll
        for (int c = t; c < 1024; c += 256) {
            const int row = c >> 4, ch = c & 15;
            const uint32_t off = row * AROW + ch * 16;
            *(uint4*)(sm + OFF_KTHI + off) = *(const uint4*)(Gh + c * 8);
            *(uint4*)(sm + OFF_KTLO + off) = *(const uint4*)(Gl + c * 8);
        }
        if (t < 128) ksum_s[t] = g_ksum[bh * 128 + t];
        else if (t < 192) P1_s[t - 128] = g_P1[bh * 64 + t - 128];
        else P2_s[t - 192] = g_P2[bh * 64 + t - 192];
    }
    const float Q1 = g_Q[bh * 2], Q2 = g_Q[bh * 2 + 1];
    __syncthreads();

    const float* Qp = g_q + (size_t)b * L_ * E_ + h * D_;
    const float angk = PI_HALF / (float)L_;
    __nv_bfloat16* qfhi = (__nv_bfloat16*)(sm + OFF_QFHI);
    __nv_bfloat16* qflo = (__nv_bfloat16*)(sm + OFF_QFLO);

    for (int r = 0; r < 16; r++) {
        const int row = w * 16 + r;
        const int pos = lbase + row;
        float sn, cs;
        __sincosf(angk * (float)(pos + 1), &sn, &cs);
        const size_t roff = (size_t)pos * E_;
        float q0 = Qp[roff + lane];
        float q1 = Qp[roff + lane + 32];
        float m = fmaxf(q0, q1);
#pragma unroll
        for (int o = 16; o; o >>= 1) m = fmaxf(m, __shfl_xor_sync(0xffffffffu, m, o));
        float e0 = __expf(q0 - m), e1 = __expf(q1 - m);
        float s = e0 + e1;
#pragma unroll
        for (int o = 16; o; o >>= 1) s += __shfl_xor_sync(0xffffffffu, s, o);
        float inv = 1.f / s;
        float s0 = e0 * inv, s1 = e1 * inv;
        float f0 = s0 * sn, f1 = s1 * sn, f2 = s0 * cs, f3 = s1 * cs;
        __nv_bfloat16 hh, ll;
        const int rb = row * 136;
        split_bf16(f0, hh, ll); qfhi[rb + lane] = hh;      qflo[rb + lane] = ll;
        split_bf16(f1, hh, ll); qfhi[rb + lane + 32] = hh; qflo[rb + lane + 32] = ll;
        split_bf16(f2, hh, ll); qfhi[rb + lane + 64] = hh; qflo[rb + lane + 64] = ll;
        split_bf16(f3, hh, ll); qfhi[rb + lane + 96] = hh; qflo[rb + lane + 96] = ll;
        float d1 = f0 * ksum_s[lane] + f1 * ksum_s[lane + 32] +
                   f2 * ksum_s[lane + 64] + f3 * ksum_s[lane + 96];
#pragma unroll
        for (int o = 16; o; o >>= 1) d1 += __shfl_xor_sync(0xffffffffu, d1, o);
        if (lane == 0) {
            float z1 = 1.f / fmaxf(d1, 1e-6f);
            float d2 = sn * Q1 + cs * Q2 + d1;
            float z2 = 1.f / fmaxf(d2, 1e-6f);
            zz_s[row] = z1 + z2;
            z2_s[row] = z2;
            sn_s[row] = sn;
            cs_s[row] = cs;
        }
    }
    __syncthreads();

    const int m0 = w * 16;
    float acc[8][4];
#pragma unroll
    for (int nt = 0; nt < 8; nt++)
#pragma unroll
        for (int j = 0; j < 4; j++) acc[nt][j] = 0.f;

    const uint32_t aoffB = sbase + (uint32_t)((m0 + (lane & 15)) * AROW + (lane >> 4) * 16);
    const uint32_t boffB = sbase + (uint32_t)(((lane & 15)) * AROW + (lane >> 4) * 16);
#pragma unroll
    for (int ks = 0; ks < 8; ks++) {
        uint32_t aH[4], aL[4], bH[4][4], bL[4][4];
        const uint32_t ao = aoffB + ks * 32;
        LDSM4(aH, ao + OFF_QFHI);
        LDSM4(aL, ao + OFF_QFLO);
#pragma unroll
        for (int nt = 0; nt < 4; nt++) {
            const uint32_t bo = boffB + nt * 16 * AROW + ks * 32;
            LDSM4(bH[nt], bo + OFF_KTHI);
            LDSM4(bL[nt], bo + OFF_KTLO);
        }
#pragma unroll
        for (int nt = 0; nt < 4; nt++) {
            MMA_BF16(acc[nt * 2],     aH, bH[nt][0], bH[nt][2]);
            MMA_BF16(acc[nt * 2],     aH, bL[nt][0], bL[nt][2]);
            MMA_BF16(acc[nt * 2],     aL, bH[nt][0], bH[nt][2]);
            MMA_BF16(acc[nt * 2 + 1], aH, bH[nt][1], bH[nt][3]);
            MMA_BF16(acc[nt * 2 + 1], aH, bL[nt][1], bL[nt][3]);
            MMA_BF16(acc[nt * 2 + 1], aL, bH[nt][1], bH[nt][3]);
        }
    }

    const int r0 = lane >> 2, cq = (lane & 3) * 2;
#pragma unroll
    for (int nt8 = 0; nt8 < 8; nt8++) {
        const int j = nt8 * 8 + cq;
        const float p1x = P1_s[j], p1y = P1_s[j + 1];
        const float p2x = P2_s[j], p2y = P2_s[j + 1];
#pragma unroll
        for (int half = 0; half < 2; half++) {
            const int row = m0 + r0 + half * 8;
            const float oz = zz_s[row], o2 = z2_s[row];
            const float sr = sn_s[row], cr = cs_s[row];
            const float px = sr * p1x + cr * p2x;
            const float py = sr * p1y + cr * p2y;
            float o0 = oz * acc[nt8][half * 2 + 0] + o2 * px;
            float o1 = oz * acc[nt8][half * 2 + 1] + o2 * py;
            const int posl = lbase + row;
            const size_t oidx = ((size_t)posl * B_ + b) * E_ + h * D_ + j;
            *(__half2*)(g_af + oidx) = __floats2half2_rn(o0, o1);
        }
    }
}

// ---------------- launch ----------------------------------------------------
extern "C" void kernel_launch(void* const* d_in, const int* in_sizes, int n_in,
                              void* d_out, int out_size) {
    const float* X  = (const float*)d_in[0];
    const float* Wq = (const float*)d_in[1];
    const float* bq = (const float*)d_in[2];
    const float* Wk = (const float*)d_in[3];
    const float* bk = (const float*)d_in[4];
    const float* Wv = (const float*)d_in[5];
    const float* bv = (const float*)d_in[6];
    const float* Wo = (const float*)d_in[7];
    const float* bo = (const float*)d_in[8];
    float* out = (float*)d_out;

    cudaFuncSetAttribute(qkv_mma, cudaFuncAttributeMaxDynamicSharedMemorySize, DSMEM);
    cudaFuncSetAttribute(oproj_mma, cudaFuncAttributeMaxDynamicSharedMemorySize, DSMEM);
    cudaFuncSetAttribute(attn_apply, cudaFuncAttributeMaxDynamicSharedMemorySize, ATTN_SMEM);

    convert_x<<<(M_ * E_) / (256 * 4), 256>>>(X);
    convert_w<<<dim3(32, 32, 4), dim3(32, 8)>>>(Wq, Wk, Wv, Wo);
    qkv_mma<<<dim3(8, 128, 3), 256, DSMEM>>>(bq, bk, bv);
    kv_reduce_part<<<dim3(NBH, NSPLIT), 256>>>();
    kv_combine<<<NBH, 256>>>();
    attn_apply<<<dim3(NBH, L_ / 128), 256, ATTN_SMEM>>>();
    oproj_mma<<<dim3(8, 128), 256, DSMEM>>>(bo, out);
}

// round 8
// speedup vs baseline: 5.2601x; 1.1932x over previous
#include <cuda_runtime.h>
#include <cuda_bf16.h>
#include <cuda_fp16.h>
#include <cstdint>

// Problem constants
#define B_  8
#define L_  2048
#define E_  1024
#define H_  16
#define D_  64
#define M_  (B_ * L_)        // 16384 rows
#define NBH (B_ * H_)        // 128 head-batches
#define NSPLIT 16
#define LSPL (L_ / NSPLIT)   // 128
#define PI_HALF 1.5707963267948966f

// ---------------- device scratch (no allocations allowed) ----------------
__device__ float g_q[(size_t)M_ * E_];
__device__ float g_k[(size_t)M_ * E_];
__device__ float g_v[(size_t)M_ * E_];
__device__ __half g_xf[(size_t)M_ * E_];           // X fp16
__device__ __half g_af[(size_t)M_ * E_];           // attn out fp16 (rows l*B+b)
__device__ __half g_wtf[4ull * E_ * E_];           // W^T fp16, per matrix [n][k]
__device__ float g_ksum[NBH * 128];
__device__ float g_P1[NBH * 64];                   // 63*sv - KS1
__device__ float g_P2[NBH * 64];                   // 63*cv - KS2
__device__ float g_Q[NBH * 2];                     // 63*ssum-S1k, 63*csum-S2k
__device__ __half g_kvtf[(size_t)NBH * 64 * 128];  // kv^T [j][i] fp16
// split partials
__device__ float g_kvp[(size_t)NSPLIT * NBH * 128 * 64];
__device__ float g_ksump[NSPLIT * NBH * 128];
__device__ float g_svp[NSPLIT * NBH * 64];
__device__ float g_cvp[NSPLIT * NBH * 64];
__device__ float g_scp[NSPLIT * NBH * 2];

// ---------------- PTX helpers ----------------------------------------------
#define CP16(dst, src) \
    asm volatile("cp.async.cg.shared.global [%0], [%1], 16;" :: "r"(dst), "l"(src))

#define LDSM4(r, addr) \
    asm volatile("ldmatrix.sync.aligned.m8n8.x4.shared.b16 {%0,%1,%2,%3}, [%4];" \
                 : "=r"((r)[0]), "=r"((r)[1]), "=r"((r)[2]), "=r"((r)[3]) : "r"(addr))

#define LDSM4T(r, addr) \
    asm volatile("ldmatrix.sync.aligned.m8n8.x4.trans.shared.b16 {%0,%1,%2,%3}, [%4];" \
                 : "=r"((r)[0]), "=r"((r)[1]), "=r"((r)[2]), "=r"((r)[3]) : "r"(addr))

#define MMA_F16(d, a, b0, b1) \
    asm volatile("mma.sync.aligned.m16n8k16.row.col.f32.f16.f16.f32 " \
                 "{%0,%1,%2,%3},{%4,%5,%6,%7},{%8,%9},{%0,%1,%2,%3};" \
                 : "+f"((d)[0]), "+f"((d)[1]), "+f"((d)[2]), "+f"((d)[3]) \
                 : "r"((a)[0]), "r"((a)[1]), "r"((a)[2]), "r"((a)[3]), \
                   "r"(b0), "r"(b1))

// ---------------- conversions ----------------------------------------------
__global__ __launch_bounds__(256) void convert_x(const float* __restrict__ X) {
    size_t i = ((size_t)blockIdx.x * 256 + threadIdx.x) * 4;
    float4 v = *(const float4*)(X + i);
    *(__half2*)(g_xf + i)     = __floats2half2_rn(v.x, v.y);
    *(__half2*)(g_xf + i + 2) = __floats2half2_rn(v.z, v.w);
}

// transpose: W[k][n] (fp32, n contiguous) -> WT[n][k] fp16
__global__ void convert_w(const float* __restrict__ Wq, const float* __restrict__ Wk,
                          const float* __restrict__ Wv, const float* __restrict__ Wo) {
    const float* W = (blockIdx.z == 0) ? Wq : (blockIdx.z == 1) ? Wk
                   : (blockIdx.z == 2) ? Wv : Wo;
    __shared__ float t[32][33];
    const int nb = blockIdx.x * 32, kb = blockIdx.y * 32;
    const int tx = threadIdx.x, ty = threadIdx.y;
#pragma unroll
    for (int i = 0; i < 4; i++)
        t[ty + 8 * i][tx] = W[(size_t)(kb + ty + 8 * i) * E_ + nb + tx];
    __syncthreads();
    __half* Of = g_wtf + (size_t)blockIdx.z * E_ * E_;
#pragma unroll
    for (int i = 0; i < 4; i++) {
        int n = nb + ty + 8 * i, k = kb + tx;
        Of[(size_t)n * E_ + k] = __float2half(t[tx][ty + 8 * i]);
    }
}

// ---------------- fp16 HMMA GEMM: C[128m,128n] = A @ B^T + bias ------------
#define BK 32
#define STAGES 3
#define TROW 80
#define TILE_BYTES (128 * TROW)        // 10240
#define STAGE_BYTES (2 * TILE_BYTES)   // A, B = 20480
#define DSMEM (STAGES * STAGE_BYTES)   // 61440
#define NCHUNK 32

__device__ __forceinline__ void gemm_tile(
    const __half* __restrict__ A, const __half* __restrict__ Bm,
    const float* __restrict__ bias, float* __restrict__ C,
    int mBase, int nBase)
{
    extern __shared__ char smem[];
    const uint32_t sbase = (uint32_t)__cvta_generic_to_shared(smem);
    const int tid = threadIdx.x;
    const int lane = tid & 31, wid = tid >> 5;
    const int wm = wid & 3, wn = wid >> 2;   // warp tile: 32m x 64n

    const __half* gp[4];
    uint32_t soff[4];
#pragma unroll
    for (int i = 0; i < 4; i++) {
        const int cid  = i * 256 + tid;
        const int tile = cid >> 9;
        const int ci   = cid & 511;
        const int row  = ci >> 2;
        const int ch   = ci & 3;
        const __half* base = (tile == 0) ? A : Bm;
        const int grow = ((tile == 0) ? mBase : nBase) + row;
        gp[i]   = base + (size_t)grow * E_ + ch * 8;
        soff[i] = (uint32_t)(tile * TILE_BYTES + row * TROW + ch * 16);
    }

    float acc[2][8][4];
#pragma unroll
    for (int mt = 0; mt < 2; mt++)
#pragma unroll
        for (int nt = 0; nt < 8; nt++)
#pragma unroll
            for (int j = 0; j < 4; j++) acc[mt][nt][j] = 0.f;

#pragma unroll
    for (int c = 0; c < 2; c++) {
        const uint32_t sb = sbase + c * STAGE_BYTES;
#pragma unroll
        for (int i = 0; i < 4; i++) CP16(sb + soff[i], gp[i] + c * BK);
        asm volatile("cp.async.commit_group;" ::: "memory");
    }

    for (int c = 0; c < NCHUNK; c++) {
        asm volatile("cp.async.wait_group 1;" ::: "memory");
        __syncthreads();

        if (c + 2 < NCHUNK) {
            const uint32_t sb = sbase + (uint32_t)(((c + 2) % STAGES) * STAGE_BYTES);
            const size_t koff = (size_t)(c + 2) * BK;
#pragma unroll
            for (int i = 0; i < 4; i++) CP16(sb + soff[i], gp[i] + koff);
        }
        asm volatile("cp.async.commit_group;" ::: "memory");

        const uint32_t st = sbase + (uint32_t)((c % STAGES) * STAGE_BYTES);
#pragma unroll
        for (int ks = 0; ks < 2; ks++) {
            uint32_t a[2][4], b[4][4];
#pragma unroll
            for (int mt = 0; mt < 2; mt++) {
                const uint32_t ad = st + (uint32_t)((wm * 32 + mt * 16 + (lane & 15)) * TROW
                                  + (ks * 2 + (lane >> 4)) * 16);
                LDSM4(a[mt], ad);
            }
#pragma unroll
            for (int nt = 0; nt < 4; nt++) {
                const uint32_t bd = st + TILE_BYTES
                                  + (uint32_t)((wn * 64 + nt * 16 + (lane & 15)) * TROW
                                  + (ks * 2 + (lane >> 4)) * 16);
                LDSM4(b[nt], bd);
            }
#pragma unroll
            for (int mt = 0; mt < 2; mt++)
#pragma unroll
                for (int nt = 0; nt < 4; nt++) {
                    MMA_F16(acc[mt][nt * 2],     a[mt], b[nt][0], b[nt][2]);
                    MMA_F16(acc[mt][nt * 2 + 1], a[mt], b[nt][1], b[nt][3]);
                }
        }
    }

    const int r0 = lane >> 2, cq = (lane & 3) * 2;
#pragma unroll
    for (int mt = 0; mt < 2; mt++)
#pragma unroll
        for (int nt8 = 0; nt8 < 8; nt8++) {
            const int col = nBase + wn * 64 + nt8 * 8 + cq;
            const float2 bv = *(const float2*)(bias + col);
            const int row = mBase + wm * 32 + mt * 16 + r0;
            float* cp0 = C + (size_t)row * E_ + col;
            *(float2*)cp0 = make_float2(acc[mt][nt8][0] + bv.x, acc[mt][nt8][1] + bv.y);
            float* cp1 = cp0 + 8 * E_;
            *(float2*)cp1 = make_float2(acc[mt][nt8][2] + bv.x, acc[mt][nt8][3] + bv.y);
        }
}

__global__ __launch_bounds__(256, 2) void qkv_mma(const float* __restrict__ bq,
                                                  const float* __restrict__ bk,
                                                  const float* __restrict__ bv) {
    const int z = blockIdx.z;
    const float* bias = (z == 0) ? bq : (z == 1) ? bk : bv;
    float* C = (z == 0) ? g_q : (z == 1) ? g_k : g_v;
    gemm_tile(g_xf, g_wtf + (size_t)z * E_ * E_,
              bias, C, blockIdx.y * 128, blockIdx.x * 128);
}

__global__ __launch_bounds__(256, 2) void oproj_mma(const float* __restrict__ bo,
                                                    float* __restrict__ out) {
    gemm_tile(g_af, g_wtf + 3ull * E_ * E_,
              bo, out, blockIdx.y * 128, blockIdx.x * 128);
}

// ---------------- KV reduction via HMMA (split over L) ---------------------
// smem: kf [128 l][272B], v [128 l][144B], reduction scratch
#define KV_KF   0
#define KV_VV   34816
#define KV_RK   53248
#define KV_RS   57344
#define KV_RC   59392
#define KV_RSC  61440
#define KV_SMEM 61504

__global__ __launch_bounds__(256) void kv_reduce_part() {
    extern __shared__ char sm[];
    const uint32_t sbase = (uint32_t)__cvta_generic_to_shared(sm);
    const int bh = blockIdx.x;
    const int sp = blockIdx.y;
    const int b = bh / H_, h = bh % H_;
    const int pbase = sp * NBH + bh;

    const int t = threadIdx.x;
    const int w = t >> 5, lane = t & 31;

    const float* Kp = g_k + (size_t)b * L_ * E_ + h * D_;
    const float* Vp = g_v + (size_t)b * L_ * E_ + h * D_;
    const float angk = PI_HALF / (float)L_;

    __half* kf_s = (__half*)(sm + KV_KF);
    __half* v_s  = (__half*)(sm + KV_VV);
    float* rk  = (float*)(sm + KV_RK);
    float* rs  = (float*)(sm + KV_RS);
    float* rc  = (float*)(sm + KV_RC);
    float* rsc = (float*)(sm + KV_RSC);

    float ka0 = 0.f, ka1 = 0.f, ka2 = 0.f, ka3 = 0.f;
    float sv0 = 0.f, sv1 = 0.f, cv0 = 0.f, cv1 = 0.f;
    float ss = 0.f, cc = 0.f;

    // phase 1: softmax K rows + stage kf/v fp16 (rows w*16 .. w*16+15)
#pragma unroll 1
    for (int r = 0; r < 16; r++) {
        const int row = w * 16 + r;
        const int pos = sp * LSPL + row;
        float sn, cs;
        __sincosf(angk * (float)(pos + 1), &sn, &cs);
        const size_t roff = (size_t)pos * E_;
        float k0 = Kp[roff + lane];
        float k1 = Kp[roff + lane + 32];
        float v0 = Vp[roff + lane];
        float v1 = Vp[roff + lane + 32];
        float m = fmaxf(k0, k1);
#pragma unroll
        for (int o = 16; o; o >>= 1) m = fmaxf(m, __shfl_xor_sync(0xffffffffu, m, o));
        float e0 = __expf(k0 - m), e1 = __expf(k1 - m);
        float s = e0 + e1;
#pragma unroll
        for (int o = 16; o; o >>= 1) s += __shfl_xor_sync(0xffffffffu, s, o);
        float inv = 1.f / s;
        float s0 = e0 * inv, s1 = e1 * inv;
        float f0 = s0 * sn, f1 = s1 * sn, f2 = s0 * cs, f3 = s1 * cs;
        __half* kr = kf_s + row * 136;
        kr[lane]      = __float2half(f0);
        kr[lane + 32] = __float2half(f1);
        kr[lane + 64] = __float2half(f2);
        kr[lane + 96] = __float2half(f3);
        __half* vr = v_s + row * 72;
        vr[lane]      = __float2half(v0);
        vr[lane + 32] = __float2half(v1);
        ka0 += f0; ka1 += f1; ka2 += f2; ka3 += f3;
        sv0 += sn * v0; sv1 += sn * v1;
        cv0 += cs * v0; cv1 += cs * v1;
        ss += sn; cc += cs;
    }
    // per-warp partials to smem
    rk[w * 128 + lane]      = ka0;
    rk[w * 128 + lane + 32] = ka1;
    rk[w * 128 + lane + 64] = ka2;
    rk[w * 128 + lane + 96] = ka3;
    rs[w * 64 + lane] = sv0; rs[w * 64 + lane + 32] = sv1;
    rc[w * 64 + lane] = cv0; rc[w * 64 + lane + 32] = cv1;
    if (lane == 0) { rsc[w * 2] = ss; rsc[w * 2 + 1] = cc; }
    __syncthreads();

    // cross-warp reductions -> global partials
    if (t < 128) {
        float s = 0.f;
#pragma unroll
        for (int ww = 0; ww < 8; ww++) s += rk[ww * 128 + t];
        g_ksump[pbase * 128 + t] = s;
    } else if (t < 192) {
        float s = 0.f;
#pragma unroll
        for (int ww = 0; ww < 8; ww++) s += rs[ww * 64 + t - 128];
        g_svp[pbase * 64 + t - 128] = s;
    } else {
        float s = 0.f;
#pragma unroll
        for (int ww = 0; ww < 8; ww++) s += rc[ww * 64 + t - 192];
        g_cvp[pbase * 64 + t - 192] = s;
    }
    if (t == 0) {
        float s = 0.f;
#pragma unroll
        for (int ww = 0; ww < 8; ww++) s += rsc[ww * 2];
        g_scp[pbase * 2] = s;
    }
    if (t == 1) {
        float s = 0.f;
#pragma unroll
        for (int ww = 0; ww < 8; ww++) s += rsc[ww * 2 + 1];
        g_scp[pbase * 2 + 1] = s;
    }

    // phase 2: kv[i][j] = sum_l kf[l][i] v[l][j] via trans-ldmatrix MMA
    const int wm = w & 3, wn = w >> 2;
    const int m_base = wm * 32, n_base = wn * 32;
    float acc[2][4][4];
#pragma unroll
    for (int mt = 0; mt < 2; mt++)
#pragma unroll
        for (int nb = 0; nb < 4; nb++)
#pragma unroll
            for (int j = 0; j < 4; j++) acc[mt][nb][j] = 0.f;

    const int krow = (lane & 7) + ((lane >> 4) << 3);   // k-dim row within chunk
    const int csel = (lane & 8);                         // col +8 select
#pragma unroll
    for (int kc = 0; kc < 8; kc++) {
        const int kb = kc * 16;
        uint32_t a[2][4], bb[2][4];
#pragma unroll
        for (int mt = 0; mt < 2; mt++) {
            const uint32_t ad = sbase + KV_KF
                + (uint32_t)((kb + krow) * 272 + (m_base + mt * 16 + csel) * 2);
            LDSM4T(a[mt], ad);
        }
#pragma unroll
        for (int nt = 0; nt < 2; nt++) {
            const uint32_t bd = sbase + KV_VV
                + (uint32_t)((kb + krow) * 144 + (n_base + nt * 16 + csel) * 2);
            LDSM4T(bb[nt], bd);
        }
#pragma unroll
        for (int mt = 0; mt < 2; mt++)
#pragma unroll
            for (int nt = 0; nt < 2; nt++) {
                MMA_F16(acc[mt][nt * 2],     a[mt], bb[nt][0], bb[nt][2]);
                MMA_F16(acc[mt][nt * 2 + 1], a[mt], bb[nt][1], bb[nt][3]);
            }
    }

    // store kv partial
    float* KVp = g_kvp + (size_t)pbase * 8192;
    const int r0 = lane >> 2, cq = (lane & 3) * 2;
#pragma unroll
    for (int mt = 0; mt < 2; mt++)
#pragma unroll
        for (int nb = 0; nb < 4; nb++) {
            const int i0 = m_base + mt * 16 + r0;
            const int j = n_base + nb * 8 + cq;
            *(float2*)(KVp + i0 * 64 + j) =
                make_float2(acc[mt][nb][0], acc[mt][nb][1]);
            *(float2*)(KVp + (i0 + 8) * 64 + j) =
                make_float2(acc[mt][nb][2], acc[mt][nb][3]);
        }
}

// combine partials; derive P1/P2/Q; emit kv^T fp16 for the apply MMA
__global__ __launch_bounds__(256) void kv_combine() {
    const int bh = blockIdx.x;
    const int t = threadIdx.x;

    __shared__ float kv_s[128 * 64];
    __shared__ float ksum_s[128];
    __shared__ float sv_s[64], cv_s[64];

#pragma unroll 4
    for (int e = t * 32; e < t * 32 + 32; e += 4) {
        float4 s = make_float4(0.f, 0.f, 0.f, 0.f);
#pragma unroll
        for (int p = 0; p < NSPLIT; p++) {
            const float4 v = *(const float4*)(g_kvp + (size_t)(p * NBH + bh) * 8192 + e);
            s.x += v.x; s.y += v.y; s.z += v.z; s.w += v.w;
        }
        *(float4*)(kv_s + e) = s;
    }
    if (t < 128) {
        float s = 0.f;
#pragma unroll
        for (int p = 0; p < NSPLIT; p++) s += g_ksump[(p * NBH + bh) * 128 + t];
        ksum_s[t] = s;
        g_ksum[bh * 128 + t] = s;
    } else if (t < 192) {
        float s = 0.f;
#pragma unroll
        for (int p = 0; p < NSPLIT; p++) s += g_svp[(p * NBH + bh) * 64 + t - 128];
        sv_s[t - 128] = s;
    } else {
        float s = 0.f;
#pragma unroll
        for (int p = 0; p < NSPLIT; p++) s += g_cvp[(p * NBH + bh) * 64 + t - 192];
        cv_s[t - 192] = s;
    }
    __syncthreads();

    // kv^T fp16: [j][i], i contiguous
    {
        const int j = t & 63;
        const int i0 = (t >> 6) * 32;
        __half* Of = g_kvtf + (size_t)bh * 8192 + j * 128;
#pragma unroll 4
        for (int i = i0; i < i0 + 32; i += 2) {
            float a = kv_s[i * 64 + j];
            float c = kv_s[(i + 1) * 64 + j];
            *(__half2*)(Of + i) = __floats2half2_rn(a, c);
        }
    }

    if (t < 64) {
        float ks1 = 0.f;
#pragma unroll 8
        for (int i = 0; i < 64; i++) ks1 += kv_s[i * 64 + t];
        g_P1[bh * 64 + t] = 63.f * sv_s[t] - ks1;
    } else if (t < 128) {
        const int j = t - 64;
        float ks2 = 0.f;
#pragma unroll 8
        for (int i = 64; i < 128; i++) ks2 += kv_s[i * 64 + j];
        g_P2[bh * 64 + j] = 63.f * cv_s[j] - ks2;
    } else if (t == 128) {
        float s1k = 0.f;
        for (int i = 0; i < 64; i++) s1k += ksum_s[i];
        float ss = 0.f;
        for (int p = 0; p < NSPLIT; p++) ss += g_scp[(p * NBH + bh) * 2];
        g_Q[bh * 2] = 63.f * ss - s1k;
    } else if (t == 129) {
        float s2k = 0.f;
        for (int i = 64; i < 128; i++) s2k += ksum_s[i];
        float cc = 0.f;
        for (int p = 0; p < NSPLIT; p++) cc += g_scp[(p * NBH + bh) * 2 + 1];
        g_Q[bh * 2 + 1] = 63.f * cc - s2k;
    }
}

// ---------------- apply via fp16 HMMA: C = qf @ kv^T, then normalize -------
#define OFF_QF   0
#define OFF_KT   34816
#define OFF_KSUM 52224
#define OFF_P1   (OFF_KSUM + 512)
#define OFF_P2   (OFF_P1 + 256)
#define OFF_ZZ   (OFF_P2 + 256)
#define OFF_Z2   (OFF_ZZ + 512)
#define OFF_SN   (OFF_Z2 + 512)
#define OFF_CS   (OFF_SN + 512)
#define ATTN_SMEM (OFF_CS + 512)   // 55296

__global__ __launch_bounds__(256) void attn_apply() {
    extern __shared__ char sm[];
    const uint32_t sbase = (uint32_t)__cvta_generic_to_shared(sm);
    const int bh = blockIdx.x;
    const int b = bh / H_, h = bh % H_;
    const int lbase = blockIdx.y * 128;
    const int t = threadIdx.x;
    const int w = t >> 5, lane = t & 31;

    float* ksum_s = (float*)(sm + OFF_KSUM);
    float* P1_s   = (float*)(sm + OFF_P1);
    float* P2_s   = (float*)(sm + OFF_P2);
    float* zz_s   = (float*)(sm + OFF_ZZ);
    float* z2_s   = (float*)(sm + OFF_Z2);
    float* sn_s   = (float*)(sm + OFF_SN);
    float* cs_s   = (float*)(sm + OFF_CS);

    {
        const __half* Gf = g_kvtf + (size_t)bh * 8192;
#pragma unroll
        for (int c = t; c < 1024; c += 256) {
            const int row = c >> 4, ch = c & 15;
            *(uint4*)(sm + OFF_KT + row * 272 + ch * 16) = *(const uint4*)(Gf + c * 8);
        }
        if (t < 128) ksum_s[t] = g_ksum[bh * 128 + t];
        else if (t < 192) P1_s[t - 128] = g_P1[bh * 64 + t - 128];
        else P2_s[t - 192] = g_P2[bh * 64 + t - 192];
    }
    const float Q1 = g_Q[bh * 2], Q2 = g_Q[bh * 2 + 1];
    __syncthreads();

    const float* Qp = g_q + (size_t)b * L_ * E_ + h * D_;
    const float angk = PI_HALF / (float)L_;
    __half* qf = (__half*)(sm + OFF_QF);

    for (int r = 0; r < 16; r++) {
        const int row = w * 16 + r;
        const int pos = lbase + row;
        float sn, cs;
        __sincosf(angk * (float)(pos + 1), &sn, &cs);
        const size_t roff = (size_t)pos * E_;
        float q0 = Qp[roff + lane];
        float q1 = Qp[roff + lane + 32];
        float m = fmaxf(q0, q1);
#pragma unroll
        for (int o = 16; o; o >>= 1) m = fmaxf(m, __shfl_xor_sync(0xffffffffu, m, o));
        float e0 = __expf(q0 - m), e1 = __expf(q1 - m);
        float s = e0 + e1;
#pragma unroll
        for (int o = 16; o; o >>= 1) s += __shfl_xor_sync(0xffffffffu, s, o);
        float inv = 1.f / s;
        float s0 = e0 * inv, s1 = e1 * inv;
        float f0 = s0 * sn, f1 = s1 * sn, f2 = s0 * cs, f3 = s1 * cs;
        __half* qr = qf + row * 136;
        qr[lane]      = __float2half(f0);
        qr[lane + 32] = __float2half(f1);
        qr[lane + 64] = __float2half(f2);
        qr[lane + 96] = __float2half(f3);
        float d1 = f0 * ksum_s[lane] + f1 * ksum_s[lane + 32] +
                   f2 * ksum_s[lane + 64] + f3 * ksum_s[lane + 96];
#pragma unroll
        for (int o = 16; o; o >>= 1) d1 += __shfl_xor_sync(0xffffffffu, d1, o);
        if (lane == 0) {
            float z1 = 1.f / fmaxf(d1, 1e-6f);
            float d2 = sn * Q1 + cs * Q2 + d1;
            float z2 = 1.f / fmaxf(d2, 1e-6f);
            zz_s[row] = z1 + z2;
            z2_s[row] = z2;
            sn_s[row] = sn;
            cs_s[row] = cs;
        }
    }
    __syncthreads();

    const int m0 = w * 16;
    float acc[8][4];
#pragma unroll
    for (int nt = 0; nt < 8; nt++)
#pragma unroll
        for (int j = 0; j < 4; j++) acc[nt][j] = 0.f;

    const uint32_t aoffB = sbase + OFF_QF
        + (uint32_t)((m0 + (lane & 15)) * 272 + (lane >> 4) * 16);
    const uint32_t boffB = sbase + OFF_KT
        + (uint32_t)((lane & 15) * 272 + (lane >> 4) * 16);
#pragma unroll
    for (int ks = 0; ks < 8; ks++) {
        uint32_t a[4], bb[4][4];
        LDSM4(a, aoffB + ks * 32);
#pragma unroll
        for (int nt = 0; nt < 4; nt++)
            LDSM4(bb[nt], boffB + nt * 16 * 272 + ks * 32);
#pragma unroll
        for (int nt = 0; nt < 4; nt++) {
            MMA_F16(acc[nt * 2],     a, bb[nt][0], bb[nt][2]);
            MMA_F16(acc[nt * 2 + 1], a, bb[nt][1], bb[nt][3]);
        }
    }

    const int r0 = lane >> 2, cq = (lane & 3) * 2;
#pragma unroll
    for (int nt8 = 0; nt8 < 8; nt8++) {
        const int j = nt8 * 8 + cq;
        const float p1x = P1_s[j], p1y = P1_s[j + 1];
        const float p2x = P2_s[j], p2y = P2_s[j + 1];
#pragma unroll
        for (int half = 0; half < 2; half++) {
            const int row = m0 + r0 + half * 8;
            const float oz = zz_s[row], o2 = z2_s[row];
            const float sr = sn_s[row], cr = cs_s[row];
            const float px = sr * p1x + cr * p2x;
            const float py = sr * p1y + cr * p2y;
            float o0 = oz * acc[nt8][half * 2 + 0] + o2 * px;
            float o1 = oz * acc[nt8][half * 2 + 1] + o2 * py;
            const int posl = lbase + row;
            const size_t oidx = ((size_t)posl * B_ + b) * E_ + h * D_ + j;
            *(__half2*)(g_af + oidx) = __floats2half2_rn(o0, o1);
        }
    }
}

// ---------------- launch ----------------------------------------------------
extern "C" void kernel_launch(void* const* d_in, const int* in_sizes, int n_in,
                              void* d_out, int out_size) {
    const float* X  = (const float*)d_in[0];
    const float* Wq = (const float*)d_in[1];
    const float* bq = (const float*)d_in[2];
    const float* Wk = (const float*)d_in[3];
    const float* bk = (const float*)d_in[4];
    const float* Wv = (const float*)d_in[5];
    const float* bv = (const float*)d_in[6];
    const float* Wo = (const float*)d_in[7];
    const float* bo = (const float*)d_in[8];
    float* out = (float*)d_out;

    cudaFuncSetAttribute(qkv_mma, cudaFuncAttributeMaxDynamicSharedMemorySize, DSMEM);
    cudaFuncSetAttribute(oproj_mma, cudaFuncAttributeMaxDynamicSharedMemorySize, DSMEM);
    cudaFuncSetAttribute(attn_apply, cudaFuncAttributeMaxDynamicSharedMemorySize, ATTN_SMEM);
    cudaFuncSetAttribute(kv_reduce_part, cudaFuncAttributeMaxDynamicSharedMemorySize, KV_SMEM);

    convert_x<<<(M_ * E_) / (256 * 4), 256>>>(X);
    convert_w<<<dim3(32, 32, 4), dim3(32, 8)>>>(Wq, Wk, Wv, Wo);
    qkv_mma<<<dim3(8, 128, 3), 256, DSMEM>>>(bq, bk, bv);
    kv_reduce_part<<<dim3(NBH, NSPLIT), 256, KV_SMEM>>>();
    kv_combine<<<NBH, 256>>>();
    attn_apply<<<dim3(NBH, L_ / 128), 256, ATTN_SMEM>>>();
    oproj_mma<<<dim3(8, 128), 256, DSMEM>>>(bo, out);
}